// round 9
// baseline (speedup 1.0000x reference)
#include <cuda_runtime.h>
#include <cuda_bf16.h>
#include <math.h>

#define NB   16
#define CI   128
#define HH   40
#define WW   200
#define PP   (HH*WW)
#define KK   64

// ------------------------- scratch (static device) -------------------------
__device__ float d_a     [NB*KK*PP];            // soft assignment [n][k][p]
__device__ float d_asum  [NB*KK];
__device__ float d_vladp [8*NB*KK*CI];          // split-K partials [s][n][k][c]
__device__ float d_pool1 [NB*256*20*100];
__device__ float d_h2    [NB*512*20*100];
__device__ float d_pool2 [NB*512*5*25];
__device__ float d_xf    [NB*1024];
__device__ float d_feat  [NB*9216];

// ---------------------- packed f32x2 helpers (Blackwell) --------------------
__device__ __forceinline__ unsigned long long dup_f32x2(float x) {
    unsigned long long d;
    unsigned int xi = __float_as_uint(x);
    asm("mov.b64 %0, {%1, %1};" : "=l"(d) : "r"(xi));
    return d;
}
__device__ __forceinline__ void fma_f32x2(unsigned long long& acc,
                                          unsigned long long a,
                                          unsigned long long b) {
    asm("fma.rn.f32x2 %0, %1, %2, %0;" : "+l"(acc) : "l"(a), "l"(b));
}
__device__ __forceinline__ float2 unpack_f32x2(unsigned long long v) {
    unsigned int lo, hi;
    asm("mov.b64 {%0, %1}, %2;" : "=r"(lo), "=r"(hi) : "l"(v));
    return make_float2(__uint_as_float(lo), __uint_as_float(hi));
}

// ---------------------------------------------------------------------------
// 1) soft-assignment: 1x1-conv logits + softmax over K.  grid(50,16), 256 thr
// ---------------------------------------------------------------------------
__global__ void __launch_bounds__(256) assign_kernel(
    const float* __restrict__ x, const float* __restrict__ cw,
    const float* __restrict__ cb)
{
    extern __shared__ float smem[];
    float* sX = smem;             // [128][160]
    float* sW = sX + 128*160;     // [64][128]
    float* sB = sW + 64*128;      // [64]
    float* sL = sB + 64;          // [64][160]

    int tid = threadIdx.x;
    int n   = blockIdx.y;
    int p0  = blockIdx.x * 160;

    for (int idx = tid; idx < 128*160; idx += 256) {
        int c = idx / 160, pp = idx - c*160;
        sX[idx] = x[((long)n*CI + c)*PP + p0 + pp];
    }
    for (int idx = tid; idx < 64*128; idx += 256) sW[idx] = cw[idx];
    if (tid < 64) sB[tid] = cb[tid];
    __syncthreads();

    int pg = tid & 31, kg = tid >> 5;
    float acc[8][5];
    #pragma unroll
    for (int o = 0; o < 8; o++) {
        float b = sB[kg*8 + o];
        #pragma unroll
        for (int j = 0; j < 5; j++) acc[o][j] = b;
    }
    for (int c = 0; c < 128; c++) {
        float xv[5];
        #pragma unroll
        for (int j = 0; j < 5; j++) xv[j] = sX[c*160 + pg*5 + j];
        #pragma unroll
        for (int o = 0; o < 8; o++) {
            float wv = sW[(kg*8 + o)*128 + c];
            #pragma unroll
            for (int j = 0; j < 5; j++) acc[o][j] += wv * xv[j];
        }
    }
    #pragma unroll
    for (int o = 0; o < 8; o++)
        #pragma unroll
        for (int j = 0; j < 5; j++)
            sL[(kg*8 + o)*160 + pg*5 + j] = acc[o][j];
    __syncthreads();

    if (tid < 160) {
        int p = tid;
        float mx = -3.4e38f;
        #pragma unroll
        for (int k = 0; k < 64; k++) mx = fmaxf(mx, sL[k*160 + p]);
        float e[64];
        float s = 0.f;
        #pragma unroll
        for (int k = 0; k < 64; k++) { e[k] = expf(sL[k*160 + p] - mx); s += e[k]; }
        float inv = 1.f / s;
        float* ap = d_a + ((long)n*KK)*PP + p0 + p;
        #pragma unroll
        for (int k = 0; k < 64; k++) ap[(long)k*PP] = e[k]*inv;
    }
}

// ---------------------------------------------------------------------------
// 2) asum[n,k] = sum_p a[n,k,p].   grid 1024, 256 thr
// ---------------------------------------------------------------------------
__global__ void asum_kernel()
{
    __shared__ float sred[256];
    int row = blockIdx.x;
    const float* ap = d_a + (long)row*PP;
    float s = 0.f;
    for (int i = threadIdx.x; i < PP; i += 256) s += ap[i];
    sred[threadIdx.x] = s; __syncthreads();
    for (int st = 128; st > 0; st >>= 1) {
        if (threadIdx.x < st) sred[threadIdx.x] += sred[threadIdx.x + st];
        __syncthreads();
    }
    if (threadIdx.x == 0) d_asum[row] = sred[0];
}

// ---------------------------------------------------------------------------
// 3) VLAD GEMM partials over pixel splits.   grid(8,16), 256 thr
// ---------------------------------------------------------------------------
__global__ void __launch_bounds__(256) vlad_kernel(const float* __restrict__ x)
{
    __shared__ float sA [64*51];
    __shared__ float sX2[128*51];
    int tid = threadIdx.x;
    int split = blockIdx.x, n = blockIdx.y;
    int cg = tid & 31, kg = tid >> 5;
    float acc[8][4];
    #pragma unroll
    for (int o = 0; o < 8; o++)
        #pragma unroll
        for (int j = 0; j < 4; j++) acc[o][j] = 0.f;

    for (int ch = 0; ch < 20; ch++) {
        int pbase = split*1000 + ch*50;
        __syncthreads();
        for (int idx = tid; idx < 64*50; idx += 256) {
            int k = idx / 50, pp = idx - k*50;
            sA[k*51 + pp] = d_a[((long)n*KK + k)*PP + pbase + pp];
        }
        for (int idx = tid; idx < 128*50; idx += 256) {
            int c = idx / 50, pp = idx - c*50;
            sX2[c*51 + pp] = x[((long)n*CI + c)*PP + pbase + pp];
        }
        __syncthreads();
        for (int pp = 0; pp < 50; pp++) {
            float av[8];
            #pragma unroll
            for (int o = 0; o < 8; o++) av[o] = sA[(kg*8 + o)*51 + pp];
            #pragma unroll
            for (int j = 0; j < 4; j++) {
                float xv = sX2[(cg + 32*j)*51 + pp];
                #pragma unroll
                for (int o = 0; o < 8; o++) acc[o][j] += av[o]*xv;
            }
        }
    }
    #pragma unroll
    for (int o = 0; o < 8; o++)
        #pragma unroll
        for (int j = 0; j < 4; j++)
            d_vladp[(((long)split*NB + n)*KK + kg*8 + o)*CI + cg + 32*j] = acc[o][j];
}

// ---------------------------------------------------------------------------
// 4) VLAD reduce + center subtraction + intra L2 norm -> feat[:, :8192]
// ---------------------------------------------------------------------------
__global__ void vladreduce_kernel(const float* __restrict__ centers)
{
    __shared__ float sred[128];
    int row = blockIdx.x;                       // n*64+k
    int n = row >> 6, k = row & 63;
    int c = threadIdx.x;
    float v = -d_asum[row]*centers[k*CI + c];
    #pragma unroll
    for (int s = 0; s < 8; s++)
        v += d_vladp[(((long)s*NB + n)*KK + k)*CI + c];
    sred[c] = v*v; __syncthreads();
    for (int st = 64; st > 0; st >>= 1) {
        if (c < st) sred[c] += sred[c + st];
        __syncthreads();
    }
    float nrm = sqrtf(sred[0]);
    d_feat[(long)n*9216 + k*CI + c] = v / fmaxf(nrm, 1e-12f);
}

// ---------------------------------------------------------------------------
// 4b) global L2 over the 8192-dim VLAD block
// ---------------------------------------------------------------------------
__global__ void __launch_bounds__(256) vladglobal_kernel()
{
    __shared__ float sr[256];
    int n = blockIdx.x, tid = threadIdx.x;
    float* f = d_feat + (long)n*9216;
    float s = 0.f;
    for (int i = tid; i < 8192; i += 256) { float v = f[i]; s += v*v; }
    sr[tid] = s; __syncthreads();
    for (int st = 128; st > 0; st >>= 1) {
        if (tid < st) sr[tid] += sr[tid + st];
        __syncthreads();
    }
    float inv = 1.f / fmaxf(sqrtf(sr[0]), 1e-12f);
    for (int i = tid; i < 8192; i += 256) f[i] *= inv;
}

// ---------------------------------------------------------------------------
// 5) conv 5x5, pad 2 — FFMA2 version. 2x2 quad x 8 oc (as 4 oc-pairs) per thr.
//    Weights in smem pre-interleaved as (w[2q], w[2q+1]) float2 pairs.
// ---------------------------------------------------------------------------
template<int CIN, int HI, int WI, int COUT, bool FUSEPOOL2>
__global__ void __launch_bounds__(160, 3) conv5x5_kernel(
    const float* __restrict__ xin, const float* __restrict__ wgt,
    const float* __restrict__ bias)
{
    constexpr int ICB   = 8;
    constexpr int TILESX = WI / 20;
    extern __shared__ float smem[];
    float* sIn = smem;                  // [ICB][8][24] = 1536 floats
    float* sW  = smem + ICB*8*24;       // pairs: [32 pairs][ICB][25][2] = 12800 floats

    int tid = threadIdx.x;
    int q = tid % 20, og = tid / 20;
    int qy = q / 10, qx = q % 10;
    int tx = blockIdx.x % TILESX, ty = blockIdx.x / TILESX;
    int oy0 = ty*4, ox0 = tx*20;
    int n = blockIdx.z, ocb = blockIdx.y;
    const float* inN = (CIN == 128) ? (xin + (long)n*CIN*HI*WI)
                                    : (d_pool1 + (long)n*CIN*HI*WI);

    unsigned long long acc2[4][4];       // [oc-pair][pixel j], lo=2q, hi=2q+1
    #pragma unroll
    for (int p = 0; p < 4; p++)
        #pragma unroll
        for (int j = 0; j < 4; j++) acc2[p][j] = 0ull;

    #pragma unroll 1
    for (int ic0 = 0; ic0 < CIN; ic0 += ICB) {
        __syncthreads();
        for (int idx = tid; idx < ICB*8*24; idx += 160) {
            int ic = idx / (8*24); int rem = idx - ic*(8*24);
            int r = rem / 24, cc = rem - r*24;
            int iy = oy0 - 2 + r, ix = ox0 - 2 + cc;
            float v = 0.f;
            if (iy >= 0 && iy < HI && ix >= 0 && ix < WI)
                v = inN[((long)(ic0 + ic))*HI*WI + iy*WI + ix];
            sIn[idx] = v;
        }
        // weights: remap o -> (pair, half), pair-interleaved layout
        const float* wB = wgt + ((long)ocb*64)*CIN*25 + (long)ic0*25;
        for (int idx = tid; idx < 64*ICB*25; idx += 160) {
            int o = idx / (ICB*25); int t = idx - o*(ICB*25);
            int pr = o >> 1, half = o & 1;        // pair 0..31
            sW[((pr*ICB + t/25)*25 + t%25)*2 + half] = wB[(long)o*CIN*25 + t];
        }
        __syncthreads();

        const unsigned long long* wp = (const unsigned long long*)sW;
        #pragma unroll 1
        for (int ic = 0; ic < ICB; ic++) {
            float xr[36];
            #pragma unroll
            for (int i = 0; i < 6; i++)
                #pragma unroll
                for (int j = 0; j < 6; j++)
                    xr[i*6 + j] = sIn[(ic*8 + 2*qy + i)*24 + 2*qx + j];
            int wbase = (og*4)*ICB*25 + ic*25;
            #pragma unroll
            for (int rs = 0; rs < 25; rs++) {
                int r = rs / 5, s = rs % 5;
                unsigned long long xd0 = dup_f32x2(xr[ r   *6 + s    ]);
                unsigned long long xd1 = dup_f32x2(xr[ r   *6 + s + 1]);
                unsigned long long xd2 = dup_f32x2(xr[(r+1)*6 + s    ]);
                unsigned long long xd3 = dup_f32x2(xr[(r+1)*6 + s + 1]);
                #pragma unroll
                for (int p = 0; p < 4; p++) {
                    unsigned long long w2 = wp[wbase + p*ICB*25 + rs];
                    fma_f32x2(acc2[p][0], w2, xd0);
                    fma_f32x2(acc2[p][1], w2, xd1);
                    fma_f32x2(acc2[p][2], w2, xd2);
                    fma_f32x2(acc2[p][3], w2, xd3);
                }
            }
        }
    }

    int ocBase = ocb*64 + og*8;
    if (FUSEPOOL2) {
        int py = ty*2 + qy, px = tx*10 + qx;
        #pragma unroll
        for (int p = 0; p < 4; p++) {
            float2 v0 = unpack_f32x2(acc2[p][0]);
            float2 v1 = unpack_f32x2(acc2[p][1]);
            float2 v2 = unpack_f32x2(acc2[p][2]);
            float2 v3 = unpack_f32x2(acc2[p][3]);
            float b0 = bias[ocBase + 2*p], b1 = bias[ocBase + 2*p + 1];
            float a, m0 = -3.4e38f, m1 = -3.4e38f;
            a = v0.x + b0; a = (a >= 0.f) ? a : 0.2f*a; m0 = fmaxf(m0, a);
            a = v1.x + b0; a = (a >= 0.f) ? a : 0.2f*a; m0 = fmaxf(m0, a);
            a = v2.x + b0; a = (a >= 0.f) ? a : 0.2f*a; m0 = fmaxf(m0, a);
            a = v3.x + b0; a = (a >= 0.f) ? a : 0.2f*a; m0 = fmaxf(m0, a);
            a = v0.y + b1; a = (a >= 0.f) ? a : 0.2f*a; m1 = fmaxf(m1, a);
            a = v1.y + b1; a = (a >= 0.f) ? a : 0.2f*a; m1 = fmaxf(m1, a);
            a = v2.y + b1; a = (a >= 0.f) ? a : 0.2f*a; m1 = fmaxf(m1, a);
            a = v3.y + b1; a = (a >= 0.f) ? a : 0.2f*a; m1 = fmaxf(m1, a);
            d_pool1[(((long)n*COUT + ocBase + 2*p    )*(HI/2) + py)*(WI/2) + px] = m0;
            d_pool1[(((long)n*COUT + ocBase + 2*p + 1)*(HI/2) + py)*(WI/2) + px] = m1;
        }
    } else {
        #pragma unroll
        for (int p = 0; p < 4; p++) {
            float b0 = bias[ocBase + 2*p], b1 = bias[ocBase + 2*p + 1];
            #pragma unroll
            for (int j = 0; j < 4; j++) {
                float2 v = unpack_f32x2(acc2[p][j]);
                int oy = oy0 + 2*qy + (j >> 1);
                int ox = ox0 + 2*qx + (j & 1);
                float a0 = v.x + b0; a0 = (a0 >= 0.f) ? a0 : 0.2f*a0;
                float a1 = v.y + b1; a1 = (a1 >= 0.f) ? a1 : 0.2f*a1;
                d_h2[(((long)n*COUT + ocBase + 2*p    )*HI + oy)*WI + ox] = a0;
                d_h2[(((long)n*COUT + ocBase + 2*p + 1)*HI + oy)*WI + ox] = a1;
            }
        }
    }
}

// ---------------------------------------------------------------------------
// 6) 4x4 maxpool: d_h2[16,512,20,100] -> d_pool2[16,512,5,25]
// ---------------------------------------------------------------------------
__global__ void pool4_kernel()
{
    int idx = blockIdx.x*256 + threadIdx.x;       // 1,024,000
    int pw = idx % 25; int t = idx / 25;
    int ph = t % 5;  t /= 5;
    int ch = t % 512; int n = t / 512;
    const float* base = d_h2 + (((long)n*512 + ch)*20 + ph*4)*100 + pw*4;
    float m = -3.4e38f;
    #pragma unroll
    for (int i = 0; i < 4; i++)
        #pragma unroll
        for (int j = 0; j < 4; j++)
            m = fmaxf(m, base[i*100 + j]);
    d_pool2[idx] = m;
}

// ---------------------------------------------------------------------------
// 7) conv3 512->1024 5x5 pad2 on 5x25 + fused global maxpool — FFMA2 version
// ---------------------------------------------------------------------------
__global__ void __launch_bounds__(200) conv3_kernel(
    const float* __restrict__ w3, const float* __restrict__ b3)
{
    constexpr int ICB = 8;
    extern __shared__ float smem[];
    float* sIn  = smem;                 // [8][9][29] = 2088
    float* sW   = sIn + ICB*9*29;       // pairs: [32][ICB][25][2] = 12800
    float* sred = sW + 32*ICB*25*2;     // [64][25] = 1600

    int tid = threadIdx.x;
    int ow = tid % 25, og = tid / 25;
    int ocb = blockIdx.x, n = blockIdx.y;

    unsigned long long acc2[4][5];       // [oc-pair][oh]
    #pragma unroll
    for (int p = 0; p < 4; p++)
        #pragma unroll
        for (int h = 0; h < 5; h++) acc2[p][h] = 0ull;

    #pragma unroll 1
    for (int ic0 = 0; ic0 < 512; ic0 += ICB) {
        __syncthreads();
        for (int idx = tid; idx < ICB*9*29; idx += 200) {
            int ic = idx / (9*29); int rem = idx - ic*(9*29);
            int i = rem / 29, cc = rem - i*29;
            int iy = i - 2, ix = cc - 2;
            float v = 0.f;
            if (iy >= 0 && iy < 5 && ix >= 0 && ix < 25)
                v = d_pool2[(((long)n*512 + ic0 + ic)*5 + iy)*25 + ix];
            sIn[idx] = v;
        }
        const float* wB = w3 + ((long)ocb*64)*512*25 + (long)ic0*25;
        for (int idx = tid; idx < 64*ICB*25; idx += 200) {
            int o = idx / (ICB*25); int t = idx - o*(ICB*25);
            int pr = o >> 1, half = o & 1;
            sW[((pr*ICB + t/25)*25 + t%25)*2 + half] = wB[(long)o*512*25 + t];
        }
        __syncthreads();

        const unsigned long long* wp = (const unsigned long long*)sW;
        #pragma unroll 1
        for (int ic = 0; ic < ICB; ic++) {
            float xr[45];                 // [9][5] column patch
            #pragma unroll
            for (int i = 0; i < 9; i++)
                #pragma unroll
                for (int j = 0; j < 5; j++)
                    xr[i*5 + j] = sIn[(ic*9 + i)*29 + ow + j];
            int wbase = (og*4)*ICB*25 + ic*25;
            #pragma unroll
            for (int rs = 0; rs < 25; rs++) {
                int r = rs / 5, s = rs % 5;
                unsigned long long xd[5];
                #pragma unroll
                for (int h = 0; h < 5; h++) xd[h] = dup_f32x2(xr[(h + r)*5 + s]);
                #pragma unroll
                for (int p = 0; p < 4; p++) {
                    unsigned long long w2 = wp[wbase + p*ICB*25 + rs];
                    #pragma unroll
                    for (int h = 0; h < 5; h++) fma_f32x2(acc2[p][h], w2, xd[h]);
                }
            }
        }
    }

    #pragma unroll
    for (int p = 0; p < 4; p++) {
        float b0 = b3[ocb*64 + og*8 + 2*p];
        float b1 = b3[ocb*64 + og*8 + 2*p + 1];
        float m0 = -3.4e38f, m1 = -3.4e38f;
        #pragma unroll
        for (int h = 0; h < 5; h++) {
            float2 v = unpack_f32x2(acc2[p][h]);
            m0 = fmaxf(m0, v.x + b0);
            m1 = fmaxf(m1, v.y + b1);
        }
        sred[(og*8 + 2*p    )*25 + ow] = m0;
        sred[(og*8 + 2*p + 1)*25 + ow] = m1;
    }
    __syncthreads();
    if (tid < 64) {
        float m = -3.4e38f;
        #pragma unroll
        for (int w = 0; w < 25; w++) m = fmaxf(m, sred[tid*25 + w]);
        d_xf[(long)n*1024 + ocb*64 + tid] = m;
    }
}

// ---------------------------------------------------------------------------
// 8) L2-normalize xf -> feat[:, 8192:9216]
// ---------------------------------------------------------------------------
__global__ void xfnorm_kernel()
{
    __shared__ float sr[256];
    int n = blockIdx.x, tid = threadIdx.x;
    float v[4]; float s = 0.f;
    #pragma unroll
    for (int i = 0; i < 4; i++) {
        v[i] = d_xf[(long)n*1024 + tid + 256*i];
        s += v[i]*v[i];
    }
    sr[tid] = s; __syncthreads();
    for (int st = 128; st > 0; st >>= 1) {
        if (tid < st) sr[tid] += sr[tid + st];
        __syncthreads();
    }
    float nrm = fmaxf(sqrtf(sr[0]), 1e-12f);
    #pragma unroll
    for (int i = 0; i < 4; i++)
        d_feat[(long)n*9216 + 8192 + tid + 256*i] = v[i] / nrm;
}

// ---------------------------------------------------------------------------
// 9) MLP 9216->256 + final L2 norm.  grid 16, 256 thr
// ---------------------------------------------------------------------------
__global__ void __launch_bounds__(256) mlp_kernel(
    const float* __restrict__ mw, const float* __restrict__ mb,
    float* __restrict__ out)
{
    __shared__ float sf[9216];
    __shared__ float sr[256];
    int n = blockIdx.x, j = threadIdx.x;
    for (int i = j; i < 9216; i += 256) sf[i] = d_feat[(long)n*9216 + i];
    __syncthreads();
    float acc = mb[j];
    const float4* wr  = (const float4*)(mw + (long)j*9216);
    const float4* sf4 = (const float4*)sf;
    for (int i = 0; i < 2304; i++) {
        float4 w4 = wr[i], f4 = sf4[i];
        acc += w4.x*f4.x + w4.y*f4.y + w4.z*f4.z + w4.w*f4.w;
    }
    sr[j] = acc*acc; __syncthreads();
    for (int st = 128; st > 0; st >>= 1) {
        if (j < st) sr[j] += sr[j + st];
        __syncthreads();
    }
    float nrm = fmaxf(sqrtf(sr[0]), 1e-12f);
    out[n*256 + j] = acc / nrm;
}

// ---------------------------------------------------------------------------
extern "C" void kernel_launch(void* const* d_in, const int* in_sizes, int n_in,
                              void* d_out, int out_size)
{
    const float* x       = (const float*)d_in[0];
    const float* centers = (const float*)d_in[1];
    const float* cw      = (const float*)d_in[2];
    const float* cb      = (const float*)d_in[3];
    const float* w1      = (const float*)d_in[4];
    const float* b1      = (const float*)d_in[5];
    const float* w2      = (const float*)d_in[6];
    const float* b2      = (const float*)d_in[7];
    const float* w3      = (const float*)d_in[8];
    const float* b3      = (const float*)d_in[9];
    const float* mw      = (const float*)d_in[10];
    const float* mb      = (const float*)d_in[11];
    float* out = (float*)d_out;

    cudaFuncSetAttribute(assign_kernel,
        cudaFuncAttributeMaxDynamicSharedMemorySize, 155904);
    cudaFuncSetAttribute(conv5x5_kernel<128,40,200,256,true>,
        cudaFuncAttributeMaxDynamicSharedMemorySize, 57600);
    cudaFuncSetAttribute(conv5x5_kernel<256,20,100,512,false>,
        cudaFuncAttributeMaxDynamicSharedMemorySize, 57600);
    cudaFuncSetAttribute(conv3_kernel,
        cudaFuncAttributeMaxDynamicSharedMemorySize, 66208);

    // NetVLAD branch
    assign_kernel<<<dim3(50,16), 256, 155904>>>(x, cw, cb);
    asum_kernel<<<1024, 256>>>();
    vlad_kernel<<<dim3(8,16), 256>>>(x);
    vladreduce_kernel<<<1024, 128>>>(centers);
    vladglobal_kernel<<<16, 256>>>();

    // CNN branch
    conv5x5_kernel<128,40,200,256,true ><<<dim3(100,4,16), 160, 57600>>>(x, w1, b1);
    conv5x5_kernel<256,20,100,512,false><<<dim3(25, 8,16), 160, 57600>>>(nullptr, w2, b2);
    pool4_kernel<<<4000, 256>>>();
    conv3_kernel<<<dim3(16,16), 200, 66208>>>(w3, b3);
    xfnorm_kernel<<<16, 256>>>();

    // head
    mlp_kernel<<<16, 256>>>(mw, mb, out);
}

// round 14
// speedup vs baseline: 2.2308x; 2.2308x over previous
#include <cuda_runtime.h>
#include <cuda_bf16.h>
#include <cstdint>
#include <math.h>

#define NB   16
#define CI   128
#define HH   40
#define WW   200
#define PP   (HH*WW)
#define KK   64

__device__ float d_a     [NB*KK*PP];
__device__ float d_asum  [NB*KK];
__device__ float d_vladp [8*NB*KK*CI];
__device__ float d_pool1 [NB*256*20*100];
__device__ float d_h2    [NB*512*20*100];
__device__ float d_pool2 [NB*512*5*25];
__device__ float d_xf    [NB*1024];
__device__ float d_feat  [NB*9216];
// bf16 hi/lo weights, layout [ocb][chunk][tap25][oc64][ic16 permuted]
__device__ __align__(16) __nv_bfloat16 d_w1h[819200],  d_w1l[819200];
__device__ __align__(16) __nv_bfloat16 d_w2h[3276800], d_w2l[3276800];

// single dynamic smem symbol for the whole TU
extern __shared__ float s_dyn[];

__device__ __forceinline__ void mma4(float& c0, float& c1, float& c2, float& c3,
    uint32_t a0, uint32_t a1, uint32_t a2, uint32_t a3, uint32_t b0, uint32_t b1)
{
    asm volatile(
        "mma.sync.aligned.m16n8k16.row.col.f32.bf16.bf16.f32 "
        "{%0,%1,%2,%3}, {%4,%5,%6,%7}, {%8,%9}, {%0,%1,%2,%3};"
        : "+f"(c0), "+f"(c1), "+f"(c2), "+f"(c3)
        : "r"(a0), "r"(a1), "r"(a2), "r"(a3), "r"(b0), "r"(b1));
}
// smem k-slot p holds ic = 2*(p>>2) + (p&1) + ((p&2)?8:0)
__device__ __forceinline__ int pos_of_ic(int ic) {
    return 4*((ic & 7) >> 1) + (ic & 1) + ((ic >> 3) << 1);
}

// ---------- weight prep: fp32 -> bf16 hi/lo, writes device globals ----------
template<int CIN>
__global__ void prep_w_k(const float* __restrict__ w)
{
    __nv_bfloat16* wh = (CIN == 128) ? d_w1h : d_w2h;
    __nv_bfloat16* wl = (CIN == 128) ? d_w1l : d_w2l;
    const long total = (CIN == 128) ? 819200L : 3276800L;
    long i = (long)blockIdx.x*256 + threadIdx.x;
    if (i >= total) return;
    int p  = (int)(i & 15);
    int o  = (int)((i >> 4) & 63);
    long t = i >> 10;
    int rs = (int)(t % 25);  t /= 25;
    int nch = CIN/16;
    int ch = (int)(t % nch); int ocb = (int)(t / nch);
    int ic = 2*(p >> 2) + (p & 1) + ((p & 2) ? 8 : 0);
    float v = w[((long)(ocb*64 + o)*CIN + ch*16 + ic)*25 + rs];
    __nv_bfloat16 h = __float2bfloat16(v);
    wh[i] = h;
    wl[i] = __float2bfloat16(v - __bfloat162float(h));
}

// accumulators as named scalars (register-resident by construction)
#define CDECL(t) float c##t##_0 = 0.f, c##t##_1 = 0.f, c##t##_2 = 0.f, c##t##_3 = 0.f

#define MMASTEP(t) do {                                                        \
    int pcol = 2*(t) + (g >> 2) + s;                                           \
    uint32_t bo = (uint32_t)((prow*25 + pcol)*32 + q*8);                       \
    uint2 bh = *(uint2*)((char*)sIH + bo);                                     \
    uint2 bl = *(uint2*)((char*)sIL + bo);                                     \
    mma4(c##t##_0, c##t##_1, c##t##_2, c##t##_3,                               \
         h01.x, h23.x, h01.y, h23.y, bh.x, bh.y);                              \
    mma4(c##t##_0, c##t##_1, c##t##_2, c##t##_3,                               \
         h01.x, h23.x, h01.y, h23.y, bl.x, bl.y);                              \
    mma4(c##t##_0, c##t##_1, c##t##_2, c##t##_3,                               \
         l01.x, l23.x, l01.y, l23.y, bh.x, bh.y);                              \
} while (0)

#define EPIP(t) do {                                                           \
    float m0 = fmaxf(c##t##_0, c##t##_1);                                      \
    float m1 = fmaxf(c##t##_2, c##t##_3);                                      \
    m0 = fmaxf(m0, __shfl_xor_sync(0xffffffffu, m0, 2));                       \
    m1 = fmaxf(m1, __shfl_xor_sync(0xffffffffu, m1, 2));                       \
    if (q < 2) {                                                               \
        float v0 = m0 + b0; v0 = (v0 >= 0.f) ? v0 : 0.2f*v0;                   \
        float v1 = m1 + b1; v1 = (v1 >= 0.f) ? v1 : 0.2f*v1;                   \
        int py = ty*2 + (q & 1), px = tx*10 + (t);                             \
        d_pool1[((long)(n*COUT + oc    )*(HI/2) + py)*(WI/2) + px] = v0;       \
        d_pool1[((long)(n*COUT + oc + 8)*(HI/2) + py)*(WI/2) + px] = v1;       \
    }                                                                          \
} while (0)

#define EPIS(t) do {                                                           \
    int nn0 = 2*q, nn1 = 2*q + 1;                                              \
    int oy_0 = oy0 + (nn0 & 3), ox_0 = ox0 + 2*(t) + (nn0 >> 2);               \
    int oy_1 = oy0 + (nn1 & 3), ox_1 = ox0 + 2*(t) + (nn1 >> 2);               \
    float v;                                                                   \
    v = c##t##_0 + b0; v = (v >= 0.f) ? v : 0.2f*v;                            \
    d_h2[((long)(n*COUT + oc    )*HI + oy_0)*WI + ox_0] = v;                   \
    v = c##t##_1 + b0; v = (v >= 0.f) ? v : 0.2f*v;                            \
    d_h2[((long)(n*COUT + oc    )*HI + oy_1)*WI + ox_1] = v;                   \
    v = c##t##_2 + b1; v = (v >= 0.f) ? v : 0.2f*v;                            \
    d_h2[((long)(n*COUT + oc + 8)*HI + oy_0)*WI + ox_0] = v;                   \
    v = c##t##_3 + b1; v = (v >= 0.f) ? v : 0.2f*v;                            \
    d_h2[((long)(n*COUT + oc + 8)*HI + oy_1)*WI + ox_1] = v;                   \
} while (0)

// ----------------- conv1/conv2: implicit GEMM via mma.sync -----------------
// tile = 4 rows x 20 cols, 64 oc/block, 128 thr (4 warps x 16 oc), 10 tiles.
// Weights read from device globals (selected by CIN) — no host symbol passing.
template<int CIN, int HI, int WI, int COUT, bool POOL>
__global__ void __launch_bounds__(128, 1) conv_mma(
    const float* __restrict__ xin, const float* __restrict__ bias)
{
    constexpr int NCH = CIN/16, TILESX = WI/20;
    const __nv_bfloat16* wh = (CIN == 128) ? d_w1h : d_w2h;
    const __nv_bfloat16* wl = (CIN == 128) ? d_w1l : d_w2l;
    __nv_bfloat16* sWH = (__nv_bfloat16*)s_dyn;      // [25][64][16]
    __nv_bfloat16* sWL = sWH + 25600;
    __nv_bfloat16* sIH = sWL + 25600;                // [8 rows][25 colstride][16]
    __nv_bfloat16* sIL = sIH + 3200;
    int tid = threadIdx.x, wid = tid >> 5, lane = tid & 31;
    int g = lane >> 2, q = lane & 3;
    int tile = blockIdx.x, ocb = blockIdx.y, n = blockIdx.z;
    int ty = tile / TILESX, tx = tile % TILESX;
    int oy0 = ty*4, ox0 = tx*20;
    const float* inN = (CIN == 128 ? xin : d_pool1) + (long)n*CIN*HI*WI;

    CDECL(0); CDECL(1); CDECL(2); CDECL(3); CDECL(4);
    CDECL(5); CDECL(6); CDECL(7); CDECL(8); CDECL(9);

    for (int ch = 0; ch < NCH; ch++) {
        if (ch) __syncthreads();
        {   // weights: straight uint4 copy (already bf16, permuted)
            const uint4* gh = (const uint4*)(wh + (long)(ocb*NCH + ch)*25600);
            const uint4* gl = (const uint4*)(wl + (long)(ocb*NCH + ch)*25600);
            uint4* dh = (uint4*)sWH; uint4* dl = (uint4*)sWL;
            for (int i = tid; i < 3200; i += 128) { dh[i] = gh[i]; dl[i] = gl[i]; }
        }
        {   // input halo 8x24: fp32 -> hi/lo, one (ic,row) per thread
            int ic = tid >> 3, row = tid & 7;
            int p = pos_of_ic(ic);
            int iy = oy0 - 2 + row;
            const float* src = inN + (long)(ch*16 + ic)*HI*WI + (long)iy*WI;
            for (int col = 0; col < 24; col++) {
                int ix = ox0 - 2 + col;
                float v = (iy >= 0 && iy < HI && ix >= 0 && ix < WI)
                        ? src[ix] : 0.f;
                __nv_bfloat16 h = __float2bfloat16(v);
                sIH[(row*25 + col)*16 + p] = h;
                sIL[(row*25 + col)*16 + p] =
                    __float2bfloat16(v - __bfloat162float(h));
            }
        }
        __syncthreads();
        for (int rs = 0; rs < 25; rs++) {
            int r = rs/5, s = rs - 5*r;
            int prow = (g & 3) + r;
            uint32_t wb = (uint32_t)(rs*2048 + wid*512 + g*32 + q*8);
            uint2 h01 = *(uint2*)((char*)sWH + wb);
            uint2 h23 = *(uint2*)((char*)sWH + wb + 256);
            uint2 l01 = *(uint2*)((char*)sWL + wb);
            uint2 l23 = *(uint2*)((char*)sWL + wb + 256);
            MMASTEP(0); MMASTEP(1); MMASTEP(2); MMASTEP(3); MMASTEP(4);
            MMASTEP(5); MMASTEP(6); MMASTEP(7); MMASTEP(8); MMASTEP(9);
        }
    }
    int oc = ocb*64 + wid*16 + g;
    float b0 = bias[oc], b1 = bias[oc + 8];
    if (POOL) {
        EPIP(0); EPIP(1); EPIP(2); EPIP(3); EPIP(4);
        EPIP(5); EPIP(6); EPIP(7); EPIP(8); EPIP(9);
    } else {
        EPIS(0); EPIS(1); EPIS(2); EPIS(3); EPIS(4);
        EPIS(5); EPIS(6); EPIS(7); EPIS(8); EPIS(9);
    }
}

// ---------- conv3 scalar (round-4 passing version) + global maxpool --------
__global__ void __launch_bounds__(200) conv3_kernel(
    const float* __restrict__ w3, const float* __restrict__ b3)
{
    constexpr int ICB = 8;
    constexpr int WROW = ICB*25 + 1;
    float* sIn  = s_dyn;
    float* sW   = sIn + ICB*9*29;
    float* sred = sW + 64*WROW;

    int tid = threadIdx.x;
    int ow = tid % 25, og = tid / 25;
    int ocb = blockIdx.x, n = blockIdx.y;

    float acc[8][5];
    #pragma unroll
    for (int o = 0; o < 8; o++)
        #pragma unroll
        for (int h = 0; h < 5; h++) acc[o][h] = 0.f;

    #pragma unroll 1
    for (int ic0 = 0; ic0 < 512; ic0 += ICB) {
        __syncthreads();
        for (int idx = tid; idx < ICB*9*29; idx += 200) {
            int ic = idx / (9*29); int rem = idx - ic*(9*29);
            int i = rem / 29, cc = rem - i*29;
            int iy = i - 2, ix = cc - 2;
            float v = 0.f;
            if (iy >= 0 && iy < 5 && ix >= 0 && ix < 25)
                v = d_pool2[(((long)n*512 + ic0 + ic)*5 + iy)*25 + ix];
            sIn[idx] = v;
        }
        const float* wB = w3 + ((long)ocb*64)*512*25 + (long)ic0*25;
        for (int idx = tid; idx < 64*ICB*25; idx += 200) {
            int o = idx / (ICB*25); int t = idx - o*(ICB*25);
            sW[o*WROW + t] = wB[(long)o*512*25 + t];
        }
        __syncthreads();

        #pragma unroll 1
        for (int ic = 0; ic < ICB; ic++) {
            float xr[45];
            #pragma unroll
            for (int i = 0; i < 9; i++)
                #pragma unroll
                for (int j = 0; j < 5; j++)
                    xr[i*5 + j] = sIn[(ic*9 + i)*29 + ow + j];
            const float* wRow = sW + og*8*WROW + ic*25;
            #pragma unroll
            for (int r = 0; r < 5; r++)
                #pragma unroll
                for (int s = 0; s < 5; s++) {
                    #pragma unroll
                    for (int o = 0; o < 8; o++) {
                        float wv = wRow[o*WROW + r*5 + s];
                        #pragma unroll
                        for (int h = 0; h < 5; h++)
                            acc[o][h] += wv * xr[(h + r)*5 + s];
                    }
                }
        }
    }
    #pragma unroll
    for (int o = 0; o < 8; o++) {
        float b = b3[ocb*64 + og*8 + o];
        float m = -3.4e38f;
        #pragma unroll
        for (int h = 0; h < 5; h++) m = fmaxf(m, acc[o][h] + b);
        sred[(og*8 + o)*25 + ow] = m;
    }
    __syncthreads();
    if (tid < 64) {
        float m = -3.4e38f;
        #pragma unroll
        for (int w = 0; w < 25; w++) m = fmaxf(m, sred[tid*25 + w]);
        d_xf[(long)n*1024 + ocb*64 + tid] = m;
    }
}

// --------------------------- NetVLAD branch --------------------------------
__global__ void __launch_bounds__(256) assign_kernel(
    const float* __restrict__ x, const float* __restrict__ cw,
    const float* __restrict__ cb)
{
    float* sX = s_dyn; float* sW = sX + 128*160;
    float* sB = sW + 64*128; float* sL = sB + 64;
    int tid = threadIdx.x, n = blockIdx.y, p0 = blockIdx.x*160;
    for (int i = tid; i < 128*160; i += 256) {
        int cch = i / 160, pp = i - cch*160;
        sX[i] = x[((long)n*CI + cch)*PP + p0 + pp];
    }
    for (int i = tid; i < 64*128; i += 256) sW[i] = cw[i];
    if (tid < 64) sB[tid] = cb[tid];
    __syncthreads();
    int pg = tid & 31, kg = tid >> 5;
    float acc[8][5];
    #pragma unroll
    for (int o = 0; o < 8; o++) {
        float b = sB[kg*8 + o];
        #pragma unroll
        for (int j = 0; j < 5; j++) acc[o][j] = b;
    }
    for (int cch = 0; cch < 128; cch++) {
        float xv[5];
        #pragma unroll
        for (int j = 0; j < 5; j++) xv[j] = sX[cch*160 + pg*5 + j];
        #pragma unroll
        for (int o = 0; o < 8; o++) {
            float wv = sW[(kg*8 + o)*128 + cch];
            #pragma unroll
            for (int j = 0; j < 5; j++) acc[o][j] += wv * xv[j];
        }
    }
    #pragma unroll
    for (int o = 0; o < 8; o++)
        #pragma unroll
        for (int j = 0; j < 5; j++)
            sL[(kg*8 + o)*160 + pg*5 + j] = acc[o][j];
    __syncthreads();
    if (tid < 160) {
        float mx = -3.4e38f;
        #pragma unroll
        for (int k = 0; k < 64; k++) mx = fmaxf(mx, sL[k*160 + tid]);
        float e[64], s = 0.f;
        #pragma unroll
        for (int k = 0; k < 64; k++) { e[k] = expf(sL[k*160 + tid] - mx); s += e[k]; }
        float inv = 1.f / s;
        float* ap = d_a + ((long)n*KK)*PP + p0 + tid;
        #pragma unroll
        for (int k = 0; k < 64; k++) ap[(long)k*PP] = e[k]*inv;
    }
}

__global__ void asum_kernel()
{
    __shared__ float sr[256];
    int row = blockIdx.x;
    const float* ap = d_a + (long)row*PP;
    float s = 0.f;
    for (int i = threadIdx.x; i < PP; i += 256) s += ap[i];
    sr[threadIdx.x] = s; __syncthreads();
    for (int st = 128; st > 0; st >>= 1) {
        if (threadIdx.x < st) sr[threadIdx.x] += sr[threadIdx.x + st];
        __syncthreads();
    }
    if (threadIdx.x == 0) d_asum[row] = sr[0];
}

__global__ void __launch_bounds__(256) vlad_kernel(const float* __restrict__ x)
{
    __shared__ float sA[64*51];
    __shared__ float sX2[128*51];
    int tid = threadIdx.x, split = blockIdx.x, n = blockIdx.y;
    int cg = tid & 31, kg = tid >> 5;
    float acc[8][4];
    #pragma unroll
    for (int o = 0; o < 8; o++)
        #pragma unroll
        for (int j = 0; j < 4; j++) acc[o][j] = 0.f;
    for (int chh = 0; chh < 20; chh++) {
        int pb = split*1000 + chh*50;
        __syncthreads();
        for (int i = tid; i < 64*50; i += 256) {
            int k = i / 50, pp = i - k*50;
            sA[k*51 + pp] = d_a[((long)n*KK + k)*PP + pb + pp];
        }
        for (int i = tid; i < 128*50; i += 256) {
            int cc = i / 50, pp = i - cc*50;
            sX2[cc*51 + pp] = x[((long)n*CI + cc)*PP + pb + pp];
        }
        __syncthreads();
        for (int pp = 0; pp < 50; pp++) {
            float av[8];
            #pragma unroll
            for (int o = 0; o < 8; o++) av[o] = sA[(kg*8 + o)*51 + pp];
            #pragma unroll
            for (int j = 0; j < 4; j++) {
                float xv = sX2[(cg + 32*j)*51 + pp];
                #pragma unroll
                for (int o = 0; o < 8; o++) acc[o][j] += av[o]*xv;
            }
        }
    }
    #pragma unroll
    for (int o = 0; o < 8; o++)
        #pragma unroll
        for (int j = 0; j < 4; j++)
            d_vladp[(((long)split*NB + n)*KK + kg*8 + o)*CI + cg + 32*j] = acc[o][j];
}

__global__ void vladreduce_kernel(const float* __restrict__ centers)
{
    __shared__ float sr[128];
    int row = blockIdx.x, n = row >> 6, k = row & 63, cc = threadIdx.x;
    float v = -d_asum[row]*centers[k*CI + cc];
    #pragma unroll
    for (int s = 0; s < 8; s++)
        v += d_vladp[(((long)s*NB + n)*KK + k)*CI + cc];
    sr[cc] = v*v; __syncthreads();
    for (int st = 64; st > 0; st >>= 1) {
        if (cc < st) sr[cc] += sr[cc + st];
        __syncthreads();
    }
    d_feat[(long)n*9216 + k*CI + cc] = v / fmaxf(sqrtf(sr[0]), 1e-12f);
}

__global__ void __launch_bounds__(256) vladglobal_kernel()
{
    __shared__ float sr[256];
    int n = blockIdx.x, tid = threadIdx.x;
    float* f = d_feat + (long)n*9216;
    float s = 0.f;
    for (int i = tid; i < 8192; i += 256) { float v = f[i]; s += v*v; }
    sr[tid] = s; __syncthreads();
    for (int st = 128; st > 0; st >>= 1) {
        if (tid < st) sr[tid] += sr[tid + st];
        __syncthreads();
    }
    float inv = 1.f / fmaxf(sqrtf(sr[0]), 1e-12f);
    for (int i = tid; i < 8192; i += 256) f[i] *= inv;
}

// ------------------------------ tail kernels -------------------------------
__global__ void pool4_kernel()
{
    int idx = blockIdx.x*256 + threadIdx.x;
    int pw = idx % 25; int t = idx / 25;
    int ph = t % 5;  t /= 5;
    int cch = t % 512; int n = t / 512;
    const float* base = d_h2 + (((long)n*512 + cch)*20 + ph*4)*100 + pw*4;
    float m = -3.4e38f;
    #pragma unroll
    for (int i = 0; i < 4; i++)
        #pragma unroll
        for (int j = 0; j < 4; j++)
            m = fmaxf(m, base[i*100 + j]);
    d_pool2[idx] = m;
}

__global__ void xfnorm_kernel()
{
    __shared__ float sr[256];
    int n = blockIdx.x, tid = threadIdx.x;
    float v[4]; float s = 0.f;
    #pragma unroll
    for (int i = 0; i < 4; i++) {
        v[i] = d_xf[(long)n*1024 + tid + 256*i];
        s += v[i]*v[i];
    }
    sr[tid] = s; __syncthreads();
    for (int st = 128; st > 0; st >>= 1) {
        if (tid < st) sr[tid] += sr[tid + st];
        __syncthreads();
    }
    float nrm = fmaxf(sqrtf(sr[0]), 1e-12f);
    #pragma unroll
    for (int i = 0; i < 4; i++)
        d_feat[(long)n*9216 + 8192 + tid + 256*i] = v[i] / nrm;
}

__global__ void __launch_bounds__(256) mlp_kernel(
    const float* __restrict__ mw, const float* __restrict__ mb,
    float* __restrict__ out)
{
    __shared__ float sf[9216];
    __shared__ float sr[256];
    int n = blockIdx.x, j = threadIdx.x;
    for (int i = j; i < 9216; i += 256) sf[i] = d_feat[(long)n*9216 + i];
    __syncthreads();
    float acc = mb[j];
    const float4* wr  = (const float4*)(mw + (long)j*9216);
    const float4* sf4 = (const float4*)sf;
    for (int i = 0; i < 2304; i++) {
        float4 w4 = wr[i], f4 = sf4[i];
        acc += w4.x*f4.x + w4.y*f4.y + w4.z*f4.z + w4.w*f4.w;
    }
    sr[j] = acc*acc; __syncthreads();
    for (int st = 128; st > 0; st >>= 1) {
        if (j < st) sr[j] += sr[j + st];
        __syncthreads();
    }
    out[n*256 + j] = acc / fmaxf(sqrtf(sr[0]), 1e-12f);
}

// ---------------------------------------------------------------------------
extern "C" void kernel_launch(void* const* d_in, const int* in_sizes, int n_in,
                              void* d_out, int out_size)
{
    const float* x       = (const float*)d_in[0];
    const float* centers = (const float*)d_in[1];
    const float* cw      = (const float*)d_in[2];
    const float* cb      = (const float*)d_in[3];
    const float* w1      = (const float*)d_in[4];
    const float* b1      = (const float*)d_in[5];
    const float* w2      = (const float*)d_in[6];
    const float* b2      = (const float*)d_in[7];
    const float* w3      = (const float*)d_in[8];
    const float* b3      = (const float*)d_in[9];
    const float* mw      = (const float*)d_in[10];
    const float* mb      = (const float*)d_in[11];
    float* out = (float*)d_out;

    cudaFuncSetAttribute(assign_kernel,
        cudaFuncAttributeMaxDynamicSharedMemorySize, 155904);
    cudaFuncSetAttribute(conv_mma<128,40,200,256,true>,
        cudaFuncAttributeMaxDynamicSharedMemorySize, 115200);
    cudaFuncSetAttribute(conv_mma<256,20,100,512,false>,
        cudaFuncAttributeMaxDynamicSharedMemorySize, 115200);
    cudaFuncSetAttribute(conv3_kernel,
        cudaFuncAttributeMaxDynamicSharedMemorySize, 66208);

    // weight prep (bf16 hi/lo, permuted) — writes device globals internally
    prep_w_k<128><<<3200, 256>>>(w1);
    prep_w_k<256><<<12800, 256>>>(w2);

    // NetVLAD branch
    assign_kernel<<<dim3(50,16), 256, 155904>>>(x, cw, cb);
    asum_kernel<<<1024, 256>>>();
    vlad_kernel<<<dim3(8,16), 256>>>(x);
    vladreduce_kernel<<<1024, 128>>>(centers);
    vladglobal_kernel<<<16, 256>>>();

    // CNN branch
    conv_mma<128,40,200,256,true ><<<dim3(100,4,16), 128, 115200>>>(x, b1);
    conv_mma<256,20,100,512,false><<<dim3(25, 8,16), 128, 115200>>>(nullptr, b2);
    pool4_kernel<<<4000, 256>>>();
    conv3_kernel<<<dim3(16,16), 200, 66208>>>(w3, b3);
    xfnorm_kernel<<<16, 256>>>();

    mlp_kernel<<<16, 256>>>(mw, mb, out);
}

// round 16
// speedup vs baseline: 2.5268x; 1.1327x over previous
#include <cuda_runtime.h>
#include <cuda_bf16.h>
#include <cstdint>
#include <math.h>

#define NB   16
#define CI   128
#define HH   40
#define WW   200
#define PP   (HH*WW)
#define KK   64

__device__ float d_a     [NB*KK*PP];
__device__ float d_asum  [NB*KK];
__device__ float d_vladp [8*NB*KK*CI];
__device__ float d_pool1 [NB*256*20*100];
__device__ float d_h2    [NB*512*20*100];
__device__ float d_pool2 [NB*512*5*25];
__device__ float d_xf    [NB*1024];
__device__ float d_feat  [NB*9216];
// bf16 hi/lo weights, layout [ocb][chunk][tap25][oc64][ic16 permuted]
__device__ __align__(16) __nv_bfloat16 d_w1h[819200],   d_w1l[819200];
__device__ __align__(16) __nv_bfloat16 d_w2h[3276800],  d_w2l[3276800];
__device__ __align__(16) __nv_bfloat16 d_w3h[13107200], d_w3l[13107200];

// single dynamic smem symbol for the whole TU
extern __shared__ float s_dyn[];

__device__ __forceinline__ void mma4(float& c0, float& c1, float& c2, float& c3,
    uint32_t a0, uint32_t a1, uint32_t a2, uint32_t a3, uint32_t b0, uint32_t b1)
{
    asm volatile(
        "mma.sync.aligned.m16n8k16.row.col.f32.bf16.bf16.f32 "
        "{%0,%1,%2,%3}, {%4,%5,%6,%7}, {%8,%9}, {%0,%1,%2,%3};"
        : "+f"(c0), "+f"(c1), "+f"(c2), "+f"(c3)
        : "r"(a0), "r"(a1), "r"(a2), "r"(a3), "r"(b0), "r"(b1));
}
// smem k-slot p holds ic = 2*(p>>2) + (p&1) + ((p&2)?8:0)
__device__ __forceinline__ int pos_of_ic(int ic) {
    return 4*((ic & 7) >> 1) + (ic & 1) + ((ic >> 3) << 1);
}

// ---------- weight prep: fp32 -> bf16 hi/lo, writes device globals ----------
template<int CIN>
__global__ void prep_w_k(const float* __restrict__ w)
{
    __nv_bfloat16* wh = (CIN == 128) ? d_w1h : (CIN == 256) ? d_w2h : d_w3h;
    __nv_bfloat16* wl = (CIN == 128) ? d_w1l : (CIN == 256) ? d_w2l : d_w3l;
    const long total = (CIN == 128) ? 819200L : (CIN == 256) ? 3276800L : 13107200L;
    long i = (long)blockIdx.x*256 + threadIdx.x;
    if (i >= total) return;
    int p  = (int)(i & 15);
    int o  = (int)((i >> 4) & 63);
    long t = i >> 10;
    int rs = (int)(t % 25);  t /= 25;
    int nch = CIN/16;
    int ch = (int)(t % nch); int ocb = (int)(t / nch);
    int ic = 2*(p >> 2) + (p & 1) + ((p & 2) ? 8 : 0);
    float v = w[((long)(ocb*64 + o)*CIN + ch*16 + ic)*25 + rs];
    __nv_bfloat16 h = __float2bfloat16(v);
    wh[i] = h;
    wl[i] = __float2bfloat16(v - __bfloat162float(h));
}

// accumulators as named scalars (register-resident by construction)
#define CDECL(t) float c##t##_0 = 0.f, c##t##_1 = 0.f, c##t##_2 = 0.f, c##t##_3 = 0.f

#define MMASTEP(t) do {                                                        \
    int pcol = 2*(t) + (g >> 2) + s;                                           \
    uint32_t bo = (uint32_t)((prow*25 + pcol)*32 + q*8);                       \
    uint2 bh = *(uint2*)((char*)sIH + bo);                                     \
    uint2 bl = *(uint2*)((char*)sIL + bo);                                     \
    mma4(c##t##_0, c##t##_1, c##t##_2, c##t##_3,                               \
         h01.x, h23.x, h01.y, h23.y, bh.x, bh.y);                              \
    mma4(c##t##_0, c##t##_1, c##t##_2, c##t##_3,                               \
         h01.x, h23.x, h01.y, h23.y, bl.x, bl.y);                              \
    mma4(c##t##_0, c##t##_1, c##t##_2, c##t##_3,                               \
         l01.x, l23.x, l01.y, l23.y, bh.x, bh.y);                              \
} while (0)

#define EPIP(t) do {                                                           \
    float m0 = fmaxf(c##t##_0, c##t##_1);                                      \
    float m1 = fmaxf(c##t##_2, c##t##_3);                                      \
    m0 = fmaxf(m0, __shfl_xor_sync(0xffffffffu, m0, 2));                       \
    m1 = fmaxf(m1, __shfl_xor_sync(0xffffffffu, m1, 2));                       \
    if (q < 2) {                                                               \
        float v0 = m0 + b0; v0 = (v0 >= 0.f) ? v0 : 0.2f*v0;                   \
        float v1 = m1 + b1; v1 = (v1 >= 0.f) ? v1 : 0.2f*v1;                   \
        int py = ty*2 + (q & 1), px = tx*10 + (t);                             \
        d_pool1[((long)(n*COUT + oc    )*(HI/2) + py)*(WI/2) + px] = v0;       \
        d_pool1[((long)(n*COUT + oc + 8)*(HI/2) + py)*(WI/2) + px] = v1;       \
    }                                                                          \
} while (0)

#define EPIS(t) do {                                                           \
    int nn0 = 2*q, nn1 = 2*q + 1;                                              \
    int oy_0 = oy0 + (nn0 & 3), ox_0 = ox0 + 2*(t) + (nn0 >> 2);               \
    int oy_1 = oy0 + (nn1 & 3), ox_1 = ox0 + 2*(t) + (nn1 >> 2);               \
    float v;                                                                   \
    v = c##t##_0 + b0; v = (v >= 0.f) ? v : 0.2f*v;                            \
    d_h2[((long)(n*COUT + oc    )*HI + oy_0)*WI + ox_0] = v;                   \
    v = c##t##_1 + b0; v = (v >= 0.f) ? v : 0.2f*v;                            \
    d_h2[((long)(n*COUT + oc    )*HI + oy_1)*WI + ox_1] = v;                   \
    v = c##t##_2 + b1; v = (v >= 0.f) ? v : 0.2f*v;                            \
    d_h2[((long)(n*COUT + oc + 8)*HI + oy_0)*WI + ox_0] = v;                   \
    v = c##t##_3 + b1; v = (v >= 0.f) ? v : 0.2f*v;                            \
    d_h2[((long)(n*COUT + oc + 8)*HI + oy_1)*WI + ox_1] = v;                   \
} while (0)

// ----------------- conv1/conv2: implicit GEMM via mma.sync -----------------
// tile = 4 rows x 20 cols, 64 oc/block, 128 thr. Weights staged in 5-tap
// groups (10,240 B each) -> smem 33,280 B -> multi-block occupancy per SM.
template<int CIN, int HI, int WI, int COUT, bool POOL>
__global__ void __launch_bounds__(128) conv_mma(
    const float* __restrict__ xin, const float* __restrict__ bias)
{
    constexpr int NCH = CIN/16, TILESX = WI/20;
    const __nv_bfloat16* wh = (CIN == 128) ? d_w1h : d_w2h;
    const __nv_bfloat16* wl = (CIN == 128) ? d_w1l : d_w2l;
    __nv_bfloat16* sWH = (__nv_bfloat16*)s_dyn;      // [5 taps][64][16] = 5120
    __nv_bfloat16* sWL = sWH + 5120;
    __nv_bfloat16* sIH = sWL + 5120;                 // [8 rows][25 colstride][16]
    __nv_bfloat16* sIL = sIH + 3200;
    int tid = threadIdx.x, wid = tid >> 5, lane = tid & 31;
    int g = lane >> 2, q = lane & 3;
    int tile = blockIdx.x, ocb = blockIdx.y, n = blockIdx.z;
    int ty = tile / TILESX, tx = tile % TILESX;
    int oy0 = ty*4, ox0 = tx*20;
    const float* inN = (CIN == 128 ? xin : d_pool1) + (long)n*CIN*HI*WI;

    CDECL(0); CDECL(1); CDECL(2); CDECL(3); CDECL(4);
    CDECL(5); CDECL(6); CDECL(7); CDECL(8); CDECL(9);

    for (int ch = 0; ch < NCH; ch++) {
        __syncthreads();   // prev chunk's input + last weight group consumed
        {   // input halo 8x24: fp32 -> hi/lo, one (ic,row) per thread
            int ic = tid >> 3, row = tid & 7;
            int p = pos_of_ic(ic);
            int iy = oy0 - 2 + row;
            const float* src = inN + (long)(ch*16 + ic)*HI*WI + (long)iy*WI;
            for (int col = 0; col < 24; col++) {
                int ix = ox0 - 2 + col;
                float v = (iy >= 0 && iy < HI && ix >= 0 && ix < WI)
                        ? src[ix] : 0.f;
                __nv_bfloat16 h = __float2bfloat16(v);
                sIH[(row*25 + col)*16 + p] = h;
                sIL[(row*25 + col)*16 + p] =
                    __float2bfloat16(v - __bfloat162float(h));
            }
        }
        for (int r = 0; r < 5; r++) {
            if (r) __syncthreads();   // prev weight group consumed
            {   // stage 5-tap weight group (hi+lo): 640 uint4 = 10,240 B each
                const uint4* gh = (const uint4*)(wh + (long)(ocb*NCH + ch)*25600 + r*5120);
                const uint4* gl = (const uint4*)(wl + (long)(ocb*NCH + ch)*25600 + r*5120);
                uint4* dh = (uint4*)sWH; uint4* dl = (uint4*)sWL;
                for (int i = tid; i < 640; i += 128) { dh[i] = gh[i]; dl[i] = gl[i]; }
            }
            __syncthreads();          // group (and input, on r==0) ready
            int prow = (g & 3) + r;
            for (int s = 0; s < 5; s++) {
                uint32_t wb = (uint32_t)(s*2048 + wid*512 + g*32 + q*8);
                uint2 h01 = *(uint2*)((char*)sWH + wb);
                uint2 h23 = *(uint2*)((char*)sWH + wb + 256);
                uint2 l01 = *(uint2*)((char*)sWL + wb);
                uint2 l23 = *(uint2*)((char*)sWL + wb + 256);
                MMASTEP(0); MMASTEP(1); MMASTEP(2); MMASTEP(3); MMASTEP(4);
                MMASTEP(5); MMASTEP(6); MMASTEP(7); MMASTEP(8); MMASTEP(9);
            }
        }
    }
    int oc = ocb*64 + wid*16 + g;
    float b0 = bias[oc], b1 = bias[oc + 8];
    if (POOL) {
        EPIP(0); EPIP(1); EPIP(2); EPIP(3); EPIP(4);
        EPIP(5); EPIP(6); EPIP(7); EPIP(8); EPIP(9);
    } else {
        EPIS(0); EPIS(1); EPIS(2); EPIS(3); EPIS(4);
        EPIS(5); EPIS(6); EPIS(7); EPIS(8); EPIS(9);
    }
}

// ---------------- conv3: mma.sync + fused global maxpool -> d_xf ------------
// grid (16 ocb, 16 n), 128 thr. 125 out px in 16 tiles of 8 (clamped loads,
// masked epilogue). Input 5x25 + halo = 9x29, hi/lo split.
#define MMASTEP3(t) do {                                                       \
    int p = (t)*8 + g; if (p > 124) p = 124;                                   \
    int prow = p % 5 + r, pcol = p / 5 + s;                                    \
    uint32_t bo = (uint32_t)((prow*29 + pcol)*32 + q*8);                       \
    uint2 bh = *(uint2*)((char*)sIH + bo);                                     \
    uint2 bl = *(uint2*)((char*)sIL + bo);                                     \
    mma4(c##t##_0, c##t##_1, c##t##_2, c##t##_3,                               \
         h01.x, h23.x, h01.y, h23.y, bh.x, bh.y);                              \
    mma4(c##t##_0, c##t##_1, c##t##_2, c##t##_3,                               \
         h01.x, h23.x, h01.y, h23.y, bl.x, bl.y);                              \
    mma4(c##t##_0, c##t##_1, c##t##_2, c##t##_3,                               \
         l01.x, l23.x, l01.y, l23.y, bh.x, bh.y);                              \
} while (0)

#define EPI3(t) do {                                                           \
    int p0e = (t)*8 + 2*q, p1e = (t)*8 + 2*q + 1;                              \
    if (p0e < 125) { m0 = fmaxf(m0, c##t##_0); m1 = fmaxf(m1, c##t##_2); }     \
    if (p1e < 125) { m0 = fmaxf(m0, c##t##_1); m1 = fmaxf(m1, c##t##_3); }     \
} while (0)

__global__ void __launch_bounds__(128) conv3_mma(const float* __restrict__ b3)
{
    __nv_bfloat16* sWH = (__nv_bfloat16*)s_dyn;      // [25][64][16]
    __nv_bfloat16* sWL = sWH + 25600;
    __nv_bfloat16* sIH = sWL + 25600;                // [9][29][16]
    __nv_bfloat16* sIL = sIH + 4176;
    int tid = threadIdx.x, wid = tid >> 5, lane = tid & 31;
    int g = lane >> 2, q = lane & 3;
    int ocb = blockIdx.x, n = blockIdx.y;

    CDECL(0);  CDECL(1);  CDECL(2);  CDECL(3);
    CDECL(4);  CDECL(5);  CDECL(6);  CDECL(7);
    CDECL(8);  CDECL(9);  CDECL(10); CDECL(11);
    CDECL(12); CDECL(13); CDECL(14); CDECL(15);

    for (int ch = 0; ch < 32; ch++) {
        if (ch) __syncthreads();
        {   // weights for all 25 taps: 3200 uint4 per h/l
            const uint4* gh = (const uint4*)(d_w3h + (long)(ocb*32 + ch)*25600);
            const uint4* gl = (const uint4*)(d_w3l + (long)(ocb*32 + ch)*25600);
            uint4* dh = (uint4*)sWH; uint4* dl = (uint4*)sWL;
            for (int i = tid; i < 3200; i += 128) { dh[i] = gh[i]; dl[i] = gl[i]; }
        }
        // input 16 ic x 9 rows x 29 cols, zero-padded halo, hi/lo
        for (int j = tid; j < 144; j += 128) {
            int ic = j / 9, row = j % 9;
            int p = pos_of_ic(ic);
            int iy = row - 2;
            const float* src = d_pool2 + ((long)(n*512 + ch*16 + ic)*5 + iy)*25;
            for (int col = 0; col < 29; col++) {
                int ix = col - 2;
                float v = (iy >= 0 && iy < 5 && ix >= 0 && ix < 25)
                        ? src[ix] : 0.f;
                __nv_bfloat16 h = __float2bfloat16(v);
                sIH[(row*29 + col)*16 + p] = h;
                sIL[(row*29 + col)*16 + p] =
                    __float2bfloat16(v - __bfloat162float(h));
            }
        }
        __syncthreads();
        for (int rs = 0; rs < 25; rs++) {
            int r = rs/5, s = rs - 5*r;
            uint32_t wb = (uint32_t)(rs*2048 + wid*512 + g*32 + q*8);
            uint2 h01 = *(uint2*)((char*)sWH + wb);
            uint2 h23 = *(uint2*)((char*)sWH + wb + 256);
            uint2 l01 = *(uint2*)((char*)sWL + wb);
            uint2 l23 = *(uint2*)((char*)sWL + wb + 256);
            MMASTEP3(0);  MMASTEP3(1);  MMASTEP3(2);  MMASTEP3(3);
            MMASTEP3(4);  MMASTEP3(5);  MMASTEP3(6);  MMASTEP3(7);
            MMASTEP3(8);  MMASTEP3(9);  MMASTEP3(10); MMASTEP3(11);
            MMASTEP3(12); MMASTEP3(13); MMASTEP3(14); MMASTEP3(15);
        }
    }
    float m0 = -3.4e38f, m1 = -3.4e38f;
    EPI3(0);  EPI3(1);  EPI3(2);  EPI3(3);
    EPI3(4);  EPI3(5);  EPI3(6);  EPI3(7);
    EPI3(8);  EPI3(9);  EPI3(10); EPI3(11);
    EPI3(12); EPI3(13); EPI3(14); EPI3(15);
    m0 = fmaxf(m0, __shfl_xor_sync(0xffffffffu, m0, 1));
    m0 = fmaxf(m0, __shfl_xor_sync(0xffffffffu, m0, 2));
    m1 = fmaxf(m1, __shfl_xor_sync(0xffffffffu, m1, 1));
    m1 = fmaxf(m1, __shfl_xor_sync(0xffffffffu, m1, 2));
    if (q == 0) {
        int oc = ocb*64 + wid*16 + g;
        d_xf[(long)n*1024 + oc    ] = m0 + b3[oc];
        d_xf[(long)n*1024 + oc + 8] = m1 + b3[oc + 8];
    }
}

// --------------------------- NetVLAD branch --------------------------------
__global__ void __launch_bounds__(256) assign_kernel(
    const float* __restrict__ x, const float* __restrict__ cw,
    const float* __restrict__ cb)
{
    float* sX = s_dyn; float* sW = sX + 128*160;
    float* sB = sW + 64*128; float* sL = sB + 64;
    int tid = threadIdx.x, n = blockIdx.y, p0 = blockIdx.x*160;
    for (int i = tid; i < 128*160; i += 256) {
        int cch = i / 160, pp = i - cch*160;
        sX[i] = x[((long)n*CI + cch)*PP + p0 + pp];
    }
    for (int i = tid; i < 64*128; i += 256) sW[i] = cw[i];
    if (tid < 64) sB[tid] = cb[tid];
    __syncthreads();
    int pg = tid & 31, kg = tid >> 5;
    float acc[8][5];
    #pragma unroll
    for (int o = 0; o < 8; o++) {
        float b = sB[kg*8 + o];
        #pragma unroll
        for (int j = 0; j < 5; j++) acc[o][j] = b;
    }
    for (int cch = 0; cch < 128; cch++) {
        float xv[5];
        #pragma unroll
        for (int j = 0; j < 5; j++) xv[j] = sX[cch*160 + pg*5 + j];
        #pragma unroll
        for (int o = 0; o < 8; o++) {
            float wv = sW[(kg*8 + o)*128 + cch];
            #pragma unroll
            for (int j = 0; j < 5; j++) acc[o][j] += wv * xv[j];
        }
    }
    #pragma unroll
    for (int o = 0; o < 8; o++)
        #pragma unroll
        for (int j = 0; j < 5; j++)
            sL[(kg*8 + o)*160 + pg*5 + j] = acc[o][j];
    __syncthreads();
    if (tid < 160) {
        float mx = -3.4e38f;
        #pragma unroll
        for (int k = 0; k < 64; k++) mx = fmaxf(mx, sL[k*160 + tid]);
        float e[64], s = 0.f;
        #pragma unroll
        for (int k = 0; k < 64; k++) { e[k] = expf(sL[k*160 + tid] - mx); s += e[k]; }
        float inv = 1.f / s;
        float* ap = d_a + ((long)n*KK)*PP + p0 + tid;
        #pragma unroll
        for (int k = 0; k < 64; k++) ap[(long)k*PP] = e[k]*inv;
    }
}

__global__ void asum_kernel()
{
    __shared__ float sr[256];
    int row = blockIdx.x;
    const float* ap = d_a + (long)row*PP;
    float s = 0.f;
    for (int i = threadIdx.x; i < PP; i += 256) s += ap[i];
    sr[threadIdx.x] = s; __syncthreads();
    for (int st = 128; st > 0; st >>= 1) {
        if (threadIdx.x < st) sr[threadIdx.x] += sr[threadIdx.x + st];
        __syncthreads();
    }
    if (threadIdx.x == 0) d_asum[row] = sr[0];
}

__global__ void __launch_bounds__(256) vlad_kernel(const float* __restrict__ x)
{
    __shared__ float sA[64*51];
    __shared__ float sX2[128*51];
    int tid = threadIdx.x, split = blockIdx.x, n = blockIdx.y;
    int cg = tid & 31, kg = tid >> 5;
    float acc[8][4];
    #pragma unroll
    for (int o = 0; o < 8; o++)
        #pragma unroll
        for (int j = 0; j < 4; j++) acc[o][j] = 0.f;
    for (int chh = 0; chh < 20; chh++) {
        int pb = split*1000 + chh*50;
        __syncthreads();
        for (int i = tid; i < 64*50; i += 256) {
            int k = i / 50, pp = i - k*50;
            sA[k*51 + pp] = d_a[((long)n*KK + k)*PP + pb + pp];
        }
        for (int i = tid; i < 128*50; i += 256) {
            int cc = i / 50, pp = i - cc*50;
            sX2[cc*51 + pp] = x[((long)n*CI + cc)*PP + pb + pp];
        }
        __syncthreads();
        for (int pp = 0; pp < 50; pp++) {
            float av[8];
            #pragma unroll
            for (int o = 0; o < 8; o++) av[o] = sA[(kg*8 + o)*51 + pp];
            #pragma unroll
            for (int j = 0; j < 4; j++) {
                float xv = sX2[(cg + 32*j)*51 + pp];
                #pragma unroll
                for (int o = 0; o < 8; o++) acc[o][j] += av[o]*xv;
            }
        }
    }
    #pragma unroll
    for (int o = 0; o < 8; o++)
        #pragma unroll
        for (int j = 0; j < 4; j++)
            d_vladp[(((long)split*NB + n)*KK + kg*8 + o)*CI + cg + 32*j] = acc[o][j];
}

__global__ void vladreduce_kernel(const float* __restrict__ centers)
{
    __shared__ float sr[128];
    int row = blockIdx.x, n = row >> 6, k = row & 63, cc = threadIdx.x;
    float v = -d_asum[row]*centers[k*CI + cc];
    #pragma unroll
    for (int s = 0; s < 8; s++)
        v += d_vladp[(((long)s*NB + n)*KK + k)*CI + cc];
    sr[cc] = v*v; __syncthreads();
    for (int st = 64; st > 0; st >>= 1) {
        if (cc < st) sr[cc] += sr[cc + st];
        __syncthreads();
    }
    d_feat[(long)n*9216 + k*CI + cc] = v / fmaxf(sqrtf(sr[0]), 1e-12f);
}

__global__ void __launch_bounds__(256) vladglobal_kernel()
{
    __shared__ float sr[256];
    int n = blockIdx.x, tid = threadIdx.x;
    float* f = d_feat + (long)n*9216;
    float s = 0.f;
    for (int i = tid; i < 8192; i += 256) { float v = f[i]; s += v*v; }
    sr[tid] = s; __syncthreads();
    for (int st = 128; st > 0; st >>= 1) {
        if (tid < st) sr[tid] += sr[tid + st];
        __syncthreads();
    }
    float inv = 1.f / fmaxf(sqrtf(sr[0]), 1e-12f);
    for (int i = tid; i < 8192; i += 256) f[i] *= inv;
}

// ------------------------------ tail kernels -------------------------------
__global__ void pool4_kernel()
{
    int idx = blockIdx.x*256 + threadIdx.x;
    int pw = idx % 25; int t = idx / 25;
    int ph = t % 5;  t /= 5;
    int cch = t % 512; int n = t / 512;
    const float* base = d_h2 + (((long)n*512 + cch)*20 + ph*4)*100 + pw*4;
    float m = -3.4e38f;
    #pragma unroll
    for (int i = 0; i < 4; i++)
        #pragma unroll
        for (int j = 0; j < 4; j++)
            m = fmaxf(m, base[i*100 + j]);
    d_pool2[idx] = m;
}

__global__ void xfnorm_kernel()
{
    __shared__ float sr[256];
    int n = blockIdx.x, tid = threadIdx.x;
    float v[4]; float s = 0.f;
    #pragma unroll
    for (int i = 0; i < 4; i++) {
        v[i] = d_xf[(long)n*1024 + tid + 256*i];
        s += v[i]*v[i];
    }
    sr[tid] = s; __syncthreads();
    for (int st = 128; st > 0; st >>= 1) {
        if (tid < st) sr[tid] += sr[tid + st];
        __syncthreads();
    }
    float nrm = fmaxf(sqrtf(sr[0]), 1e-12f);
    #pragma unroll
    for (int i = 0; i < 4; i++)
        d_feat[(long)n*9216 + 8192 + tid + 256*i] = v[i] / nrm;
}

__global__ void __launch_bounds__(256) mlp_kernel(
    const float* __restrict__ mw, const float* __restrict__ mb,
    float* __restrict__ out)
{
    __shared__ float sf[9216];
    __shared__ float sr[256];
    int n = blockIdx.x, j = threadIdx.x;
    for (int i = j; i < 9216; i += 256) sf[i] = d_feat[(long)n*9216 + i];
    __syncthreads();
    float acc = mb[j];
    const float4* wr  = (const float4*)(mw + (long)j*9216);
    const float4* sf4 = (const float4*)sf;
    for (int i = 0; i < 2304; i++) {
        float4 w4 = wr[i], f4 = sf4[i];
        acc += w4.x*f4.x + w4.y*f4.y + w4.z*f4.z + w4.w*f4.w;
    }
    sr[j] = acc*acc; __syncthreads();
    for (int st = 128; st > 0; st >>= 1) {
        if (j < st) sr[j] += sr[j + st];
        __syncthreads();
    }
    out[n*256 + j] = acc / fmaxf(sqrtf(sr[0]), 1e-12f);
}

// ---------------------------------------------------------------------------
extern "C" void kernel_launch(void* const* d_in, const int* in_sizes, int n_in,
                              void* d_out, int out_size)
{
    const float* x       = (const float*)d_in[0];
    const float* centers = (const float*)d_in[1];
    const float* cw      = (const float*)d_in[2];
    const float* cb      = (const float*)d_in[3];
    const float* w1      = (const float*)d_in[4];
    const float* b1      = (const float*)d_in[5];
    const float* w2      = (const float*)d_in[6];
    const float* b2      = (const float*)d_in[7];
    const float* w3      = (const float*)d_in[8];
    const float* b3      = (const float*)d_in[9];
    const float* mw      = (const float*)d_in[10];
    const float* mb      = (const float*)d_in[11];
    float* out = (float*)d_out;

    cudaFuncSetAttribute(assign_kernel,
        cudaFuncAttributeMaxDynamicSharedMemorySize, 155904);
    cudaFuncSetAttribute(conv3_mma,
        cudaFuncAttributeMaxDynamicSharedMemorySize, 119104);

    // weight prep (bf16 hi/lo, permuted) — writes device globals internally
    prep_w_k<128><<<3200, 256>>>(w1);
    prep_w_k<256><<<12800, 256>>>(w2);
    prep_w_k<512><<<51200, 256>>>(w3);

    // NetVLAD branch
    assign_kernel<<<dim3(50,16), 256, 155904>>>(x, cw, cb);
    asum_kernel<<<1024, 256>>>();
    vlad_kernel<<<dim3(8,16), 256>>>(x);
    vladreduce_kernel<<<1024, 128>>>(centers);
    vladglobal_kernel<<<16, 256>>>();

    // CNN branch
    conv_mma<128,40,200,256,true ><<<dim3(100,4,16), 128, 33280>>>(x, b1);
    conv_mma<256,20,100,512,false><<<dim3(25, 8,16), 128, 33280>>>(nullptr, b2);
    pool4_kernel<<<4000, 256>>>();
    conv3_mma<<<dim3(16,16), 128, 119104>>>(b3);
    xfnorm_kernel<<<16, 256>>>();

    mlp_kernel<<<16, 256>>>(mw, mb, out);
}

// round 17
// speedup vs baseline: 3.0238x; 1.1967x over previous
#include <cuda_runtime.h>
#include <cuda_bf16.h>
#include <cuda_fp16.h>
#include <cstdint>
#include <math.h>

#define NB   16
#define CI   128
#define HH   40
#define WW   200
#define PP   (HH*WW)
#define KK   64

__device__ float d_a     [NB*KK*PP];
__device__ float d_asum  [NB*KK];
__device__ float d_vladp [8*NB*KK*CI];
__device__ float d_pool1 [NB*256*20*100];
__device__ float d_pool2 [NB*512*5*25];
__device__ float d_xf    [NB*1024];
__device__ float d_feat  [NB*9216];
// conv1/conv2: fp16 hi/lo weights; conv3: bf16 hi/lo.
// layout [ocb][chunk][tap25][oc64][ic16 permuted]
__device__ __align__(16) __half        d_w1h[819200],   d_w1l[819200];
__device__ __align__(16) __half        d_w2h[3276800],  d_w2l[3276800];
__device__ __align__(16) __nv_bfloat16 d_w3h[13107200], d_w3l[13107200];

extern __shared__ float s_dyn[];

__device__ __forceinline__ void mma4h(float& c0, float& c1, float& c2, float& c3,
    uint32_t a0, uint32_t a1, uint32_t a2, uint32_t a3, uint32_t b0, uint32_t b1)
{
    asm volatile(
        "mma.sync.aligned.m16n8k16.row.col.f32.f16.f16.f32 "
        "{%0,%1,%2,%3}, {%4,%5,%6,%7}, {%8,%9}, {%0,%1,%2,%3};"
        : "+f"(c0), "+f"(c1), "+f"(c2), "+f"(c3)
        : "r"(a0), "r"(a1), "r"(a2), "r"(a3), "r"(b0), "r"(b1));
}
__device__ __forceinline__ void mma4b(float& c0, float& c1, float& c2, float& c3,
    uint32_t a0, uint32_t a1, uint32_t a2, uint32_t a3, uint32_t b0, uint32_t b1)
{
    asm volatile(
        "mma.sync.aligned.m16n8k16.row.col.f32.bf16.bf16.f32 "
        "{%0,%1,%2,%3}, {%4,%5,%6,%7}, {%8,%9}, {%0,%1,%2,%3};"
        : "+f"(c0), "+f"(c1), "+f"(c2), "+f"(c3)
        : "r"(a0), "r"(a1), "r"(a2), "r"(a3), "r"(b0), "r"(b1));
}
// smem k-slot p holds ic = 2*(p>>2) + (p&1) + ((p&2)?8:0)
__device__ __forceinline__ int pos_of_ic(int ic) {
    return 4*((ic & 7) >> 1) + (ic & 1) + ((ic >> 3) << 1);
}

// ---------- weight prep: fp32 -> fp16 hi/lo (conv1/conv2) ----------
template<int CIN>
__global__ void prep_w_h(const float* __restrict__ w)
{
    __half* wh = (CIN == 128) ? d_w1h : d_w2h;
    __half* wl = (CIN == 128) ? d_w1l : d_w2l;
    const long total = (CIN == 128) ? 819200L : 3276800L;
    long i = (long)blockIdx.x*256 + threadIdx.x;
    if (i >= total) return;
    int p  = (int)(i & 15);
    int o  = (int)((i >> 4) & 63);
    long t = i >> 10;
    int rs = (int)(t % 25);  t /= 25;
    int nch = CIN/16;
    int ch = (int)(t % nch); int ocb = (int)(t / nch);
    int ic = 2*(p >> 2) + (p & 1) + ((p & 2) ? 8 : 0);
    float v = w[((long)(ocb*64 + o)*CIN + ch*16 + ic)*25 + rs];
    __half h = __float2half_rn(v);
    wh[i] = h;
    wl[i] = __float2half_rn(v - __half2float(h));
}

// ---------- weight prep: fp32 -> bf16 hi/lo (conv3) ----------
__global__ void prep_w3(const float* __restrict__ w)
{
    long i = (long)blockIdx.x*256 + threadIdx.x;
    if (i >= 13107200L) return;
    int p  = (int)(i & 15);
    int o  = (int)((i >> 4) & 63);
    long t = i >> 10;
    int rs = (int)(t % 25);  t /= 25;
    int ch = (int)(t % 32); int ocb = (int)(t / 32);
    int ic = 2*(p >> 2) + (p & 1) + ((p & 2) ? 8 : 0);
    float v = w[((long)(ocb*64 + o)*512 + ch*16 + ic)*25 + rs];
    __nv_bfloat16 h = __float2bfloat16(v);
    d_w3h[i] = h;
    d_w3l[i] = __float2bfloat16(v - __bfloat162float(h));
}

#define CDECL(t) float c##t##_0 = 0.f, c##t##_1 = 0.f, c##t##_2 = 0.f, c##t##_3 = 0.f

// fp16 2-term: (w_h + w_l) x single-fp16 input
#define MMASTEP(t) do {                                                        \
    int pcol = 2*(t) + (g >> 2) + s;                                           \
    uint32_t bo = (uint32_t)((prow*25 + pcol)*32 + q*8);                       \
    uint2 bx = *(uint2*)((char*)sIX + bo);                                     \
    mma4h(c##t##_0, c##t##_1, c##t##_2, c##t##_3,                              \
          h01.x, h23.x, h01.y, h23.y, bx.x, bx.y);                             \
    mma4h(c##t##_0, c##t##_1, c##t##_2, c##t##_3,                              \
          l01.x, l23.x, l01.y, l23.y, bx.x, bx.y);                             \
} while (0)

#define EPIP(t) do {                                                           \
    float m0 = fmaxf(c##t##_0, c##t##_1);                                      \
    float m1 = fmaxf(c##t##_2, c##t##_3);                                      \
    m0 = fmaxf(m0, __shfl_xor_sync(0xffffffffu, m0, 2));                       \
    m1 = fmaxf(m1, __shfl_xor_sync(0xffffffffu, m1, 2));                       \
    if (q < 2) {                                                               \
        float v0 = m0 + b0; v0 = (v0 >= 0.f) ? v0 : 0.2f*v0;                   \
        float v1 = m1 + b1; v1 = (v1 >= 0.f) ? v1 : 0.2f*v1;                   \
        int py = ty*2 + (q & 1), px = tx*10 + (t);                             \
        d_pool1[((long)(n*COUT + oc    )*(HI/2) + py)*(WI/2) + px] = v0;       \
        d_pool1[((long)(n*COUT + oc + 8)*(HI/2) + py)*(WI/2) + px] = v1;       \
    }                                                                          \
} while (0)

// conv2 epilogue: 4x4 maxpool over tiles {ta,tb} x all 4 rows -> d_pool2
#define EPIQ(u, ta, tb) do {                                                   \
    float m0 = fmaxf(fmaxf(c##ta##_0, c##ta##_1),                              \
                     fmaxf(c##tb##_0, c##tb##_1));                             \
    float m1 = fmaxf(fmaxf(c##ta##_2, c##ta##_3),                              \
                     fmaxf(c##tb##_2, c##tb##_3));                             \
    m0 = fmaxf(m0, __shfl_xor_sync(0xffffffffu, m0, 1));                       \
    m0 = fmaxf(m0, __shfl_xor_sync(0xffffffffu, m0, 2));                       \
    m1 = fmaxf(m1, __shfl_xor_sync(0xffffffffu, m1, 1));                       \
    m1 = fmaxf(m1, __shfl_xor_sync(0xffffffffu, m1, 2));                       \
    if (q == 0) {                                                              \
        float v0 = m0 + b0; v0 = (v0 >= 0.f) ? v0 : 0.2f*v0;                   \
        float v1 = m1 + b1; v1 = (v1 >= 0.f) ? v1 : 0.2f*v1;                   \
        d_pool2[((long)(n*COUT + oc    )*5 + ty)*25 + tx*5 + (u)] = v0;        \
        d_pool2[((long)(n*COUT + oc + 8)*5 + ty)*25 + tx*5 + (u)] = v1;        \
    }                                                                          \
} while (0)

// ----------------- conv1/conv2: implicit GEMM via mma.sync (fp16) ----------
// tile = 4 rows x 20 cols, 64 oc/block, 128 thr. smem 26,880 B.
template<int CIN, int HI, int WI, int COUT, bool POOL>
__global__ void __launch_bounds__(128) conv_mma(
    const float* __restrict__ xin, const float* __restrict__ bias)
{
    constexpr int NCH = CIN/16, TILESX = WI/20;
    const __half* wh = (CIN == 128) ? d_w1h : d_w2h;
    const __half* wl = (CIN == 128) ? d_w1l : d_w2l;
    __half* sWH = (__half*)s_dyn;        // [5 taps][64][16] = 5120
    __half* sWL = sWH + 5120;
    __half* sIX = sWL + 5120;            // [8 rows][25 colstride][16] = 3200
    int tid = threadIdx.x, wid = tid >> 5, lane = tid & 31;
    int g = lane >> 2, q = lane & 3;
    int tile = blockIdx.x, ocb = blockIdx.y, n = blockIdx.z;
    int ty = tile / TILESX, tx = tile % TILESX;
    int oy0 = ty*4, ox0 = tx*20;
    const float* inN = (CIN == 128 ? xin : d_pool1) + (long)n*CIN*HI*WI;

    CDECL(0); CDECL(1); CDECL(2); CDECL(3); CDECL(4);
    CDECL(5); CDECL(6); CDECL(7); CDECL(8); CDECL(9);

    for (int ch = 0; ch < NCH; ch++) {
        __syncthreads();
        {   // input halo 8x24 fp16, one (ic,row) per thread
            int ic = tid >> 3, row = tid & 7;
            int p = pos_of_ic(ic);
            int iy = oy0 - 2 + row;
            const float* src = inN + (long)(ch*16 + ic)*HI*WI + (long)iy*WI;
            for (int col = 0; col < 24; col++) {
                int ix = ox0 - 2 + col;
                float v = (iy >= 0 && iy < HI && ix >= 0 && ix < WI)
                        ? src[ix] : 0.f;
                sIX[(row*25 + col)*16 + p] = __float2half_rn(v);
            }
        }
        for (int r = 0; r < 5; r++) {
            if (r) __syncthreads();
            {   // 5-tap weight group hi+lo: 640 uint4 each
                const uint4* gh = (const uint4*)(wh + (long)(ocb*NCH + ch)*25600 + r*5120);
                const uint4* gl = (const uint4*)(wl + (long)(ocb*NCH + ch)*25600 + r*5120);
                uint4* dh = (uint4*)sWH; uint4* dl = (uint4*)sWL;
                for (int i = tid; i < 640; i += 128) { dh[i] = gh[i]; dl[i] = gl[i]; }
            }
            __syncthreads();
            int prow = (g & 3) + r;
            for (int s = 0; s < 5; s++) {
                uint32_t wb = (uint32_t)(s*2048 + wid*512 + g*32 + q*8);
                uint2 h01 = *(uint2*)((char*)sWH + wb);
                uint2 h23 = *(uint2*)((char*)sWH + wb + 256);
                uint2 l01 = *(uint2*)((char*)sWL + wb);
                uint2 l23 = *(uint2*)((char*)sWL + wb + 256);
                MMASTEP(0); MMASTEP(1); MMASTEP(2); MMASTEP(3); MMASTEP(4);
                MMASTEP(5); MMASTEP(6); MMASTEP(7); MMASTEP(8); MMASTEP(9);
            }
        }
    }
    int oc = ocb*64 + wid*16 + g;
    float b0 = bias[oc], b1 = bias[oc + 8];
    if (POOL) {
        EPIP(0); EPIP(1); EPIP(2); EPIP(3); EPIP(4);
        EPIP(5); EPIP(6); EPIP(7); EPIP(8); EPIP(9);
    } else {
        EPIQ(0, 0, 1); EPIQ(1, 2, 3); EPIQ(2, 4, 5);
        EPIQ(3, 6, 7); EPIQ(4, 8, 9);
    }
}

// ---------------- conv3: bf16 3-term mma.sync + global maxpool --------------
#define MMASTEP3(t) do {                                                       \
    int p = (t)*8 + g; if (p > 124) p = 124;                                   \
    int prow = p % 5 + r, pcol = p / 5 + s;                                    \
    uint32_t bo = (uint32_t)((prow*29 + pcol)*32 + q*8);                       \
    uint2 bh = *(uint2*)((char*)sIH + bo);                                     \
    uint2 bl = *(uint2*)((char*)sIL + bo);                                     \
    mma4b(c##t##_0, c##t##_1, c##t##_2, c##t##_3,                              \
          h01.x, h23.x, h01.y, h23.y, bh.x, bh.y);                             \
    mma4b(c##t##_0, c##t##_1, c##t##_2, c##t##_3,                              \
          h01.x, h23.x, h01.y, h23.y, bl.x, bl.y);                             \
    mma4b(c##t##_0, c##t##_1, c##t##_2, c##t##_3,                              \
          l01.x, l23.x, l01.y, l23.y, bh.x, bh.y);                             \
} while (0)

#define EPI3(t) do {                                                           \
    int p0e = (t)*8 + 2*q, p1e = (t)*8 + 2*q + 1;                              \
    if (p0e < 125) { m0 = fmaxf(m0, c##t##_0); m1 = fmaxf(m1, c##t##_2); }     \
    if (p1e < 125) { m0 = fmaxf(m0, c##t##_1); m1 = fmaxf(m1, c##t##_3); }     \
} while (0)

__global__ void __launch_bounds__(128) conv3_mma(const float* __restrict__ b3)
{
    __nv_bfloat16* sWH = (__nv_bfloat16*)s_dyn;      // [25][64][16]
    __nv_bfloat16* sWL = sWH + 25600;
    __nv_bfloat16* sIH = sWL + 25600;                // [9][29][16]
    __nv_bfloat16* sIL = sIH + 4176;
    int tid = threadIdx.x, wid = tid >> 5, lane = tid & 31;
    int g = lane >> 2, q = lane & 3;
    int ocb = blockIdx.x, n = blockIdx.y;

    CDECL(0);  CDECL(1);  CDECL(2);  CDECL(3);
    CDECL(4);  CDECL(5);  CDECL(6);  CDECL(7);
    CDECL(8);  CDECL(9);  CDECL(10); CDECL(11);
    CDECL(12); CDECL(13); CDECL(14); CDECL(15);

    for (int ch = 0; ch < 32; ch++) {
        if (ch) __syncthreads();
        {
            const uint4* gh = (const uint4*)(d_w3h + (long)(ocb*32 + ch)*25600);
            const uint4* gl = (const uint4*)(d_w3l + (long)(ocb*32 + ch)*25600);
            uint4* dh = (uint4*)sWH; uint4* dl = (uint4*)sWL;
            for (int i = tid; i < 3200; i += 128) { dh[i] = gh[i]; dl[i] = gl[i]; }
        }
        for (int j = tid; j < 144; j += 128) {
            int ic = j / 9, row = j % 9;
            int p = pos_of_ic(ic);
            int iy = row - 2;
            const float* src = d_pool2 + ((long)(n*512 + ch*16 + ic)*5 + iy)*25;
            for (int col = 0; col < 29; col++) {
                int ix = col - 2;
                float v = (iy >= 0 && iy < 5 && ix >= 0 && ix < 25)
                        ? src[ix] : 0.f;
                __nv_bfloat16 h = __float2bfloat16(v);
                sIH[(row*29 + col)*16 + p] = h;
                sIL[(row*29 + col)*16 + p] =
                    __float2bfloat16(v - __bfloat162float(h));
            }
        }
        __syncthreads();
        for (int rs = 0; rs < 25; rs++) {
            int r = rs/5, s = rs - 5*r;
            uint32_t wb = (uint32_t)(rs*2048 + wid*512 + g*32 + q*8);
            uint2 h01 = *(uint2*)((char*)sWH + wb);
            uint2 h23 = *(uint2*)((char*)sWH + wb + 256);
            uint2 l01 = *(uint2*)((char*)sWL + wb);
            uint2 l23 = *(uint2*)((char*)sWL + wb + 256);
            MMASTEP3(0);  MMASTEP3(1);  MMASTEP3(2);  MMASTEP3(3);
            MMASTEP3(4);  MMASTEP3(5);  MMASTEP3(6);  MMASTEP3(7);
            MMASTEP3(8);  MMASTEP3(9);  MMASTEP3(10); MMASTEP3(11);
            MMASTEP3(12); MMASTEP3(13); MMASTEP3(14); MMASTEP3(15);
        }
    }
    float m0 = -3.4e38f, m1 = -3.4e38f;
    EPI3(0);  EPI3(1);  EPI3(2);  EPI3(3);
    EPI3(4);  EPI3(5);  EPI3(6);  EPI3(7);
    EPI3(8);  EPI3(9);  EPI3(10); EPI3(11);
    EPI3(12); EPI3(13); EPI3(14); EPI3(15);
    m0 = fmaxf(m0, __shfl_xor_sync(0xffffffffu, m0, 1));
    m0 = fmaxf(m0, __shfl_xor_sync(0xffffffffu, m0, 2));
    m1 = fmaxf(m1, __shfl_xor_sync(0xffffffffu, m1, 1));
    m1 = fmaxf(m1, __shfl_xor_sync(0xffffffffu, m1, 2));
    if (q == 0) {
        int oc = ocb*64 + wid*16 + g;
        d_xf[(long)n*1024 + oc    ] = m0 + b3[oc];
        d_xf[(long)n*1024 + oc + 8] = m1 + b3[oc + 8];
    }
}

// --------------------------- NetVLAD branch --------------------------------
__global__ void __launch_bounds__(256) assign_kernel(
    const float* __restrict__ x, const float* __restrict__ cw,
    const float* __restrict__ cb)
{
    float* sX = s_dyn; float* sW = sX + 128*160;
    float* sB = sW + 64*128; float* sL = sB + 64;
    int tid = threadIdx.x, n = blockIdx.y, p0 = blockIdx.x*160;
    for (int i = tid; i < 128*160; i += 256) {
        int cch = i / 160, pp = i - cch*160;
        sX[i] = x[((long)n*CI + cch)*PP + p0 + pp];
    }
    for (int i = tid; i < 64*128; i += 256) sW[i] = cw[i];
    if (tid < 64) sB[tid] = cb[tid];
    __syncthreads();
    int pg = tid & 31, kg = tid >> 5;
    float acc[8][5];
    #pragma unroll
    for (int o = 0; o < 8; o++) {
        float b = sB[kg*8 + o];
        #pragma unroll
        for (int j = 0; j < 5; j++) acc[o][j] = b;
    }
    for (int cch = 0; cch < 128; cch++) {
        float xv[5];
        #pragma unroll
        for (int j = 0; j < 5; j++) xv[j] = sX[cch*160 + pg*5 + j];
        #pragma unroll
        for (int o = 0; o < 8; o++) {
            float wv = sW[(kg*8 + o)*128 + cch];
            #pragma unroll
            for (int j = 0; j < 5; j++) acc[o][j] += wv * xv[j];
        }
    }
    #pragma unroll
    for (int o = 0; o < 8; o++)
        #pragma unroll
        for (int j = 0; j < 5; j++)
            sL[(kg*8 + o)*160 + pg*5 + j] = acc[o][j];
    __syncthreads();
    if (tid < 160) {
        float mx = -3.4e38f;
        #pragma unroll
        for (int k = 0; k < 64; k++) mx = fmaxf(mx, sL[k*160 + tid]);
        float e[64], s = 0.f;
        #pragma unroll
        for (int k = 0; k < 64; k++) { e[k] = expf(sL[k*160 + tid] - mx); s += e[k]; }
        float inv = 1.f / s;
        float* ap = d_a + ((long)n*KK)*PP + p0 + tid;
        #pragma unroll
        for (int k = 0; k < 64; k++) ap[(long)k*PP] = e[k]*inv;
    }
}

__global__ void asum_kernel()
{
    __shared__ float sr[256];
    int row = blockIdx.x;
    const float* ap = d_a + (long)row*PP;
    float s = 0.f;
    for (int i = threadIdx.x; i < PP; i += 256) s += ap[i];
    sr[threadIdx.x] = s; __syncthreads();
    for (int st = 128; st > 0; st >>= 1) {
        if (threadIdx.x < st) sr[threadIdx.x] += sr[threadIdx.x + st];
        __syncthreads();
    }
    if (threadIdx.x == 0) d_asum[row] = sr[0];
}

__global__ void __launch_bounds__(256) vlad_kernel(const float* __restrict__ x)
{
    __shared__ float sA[64*51];
    __shared__ float sX2[128*51];
    int tid = threadIdx.x, split = blockIdx.x, n = blockIdx.y;
    int cg = tid & 31, kg = tid >> 5;
    float acc[8][4];
    #pragma unroll
    for (int o = 0; o < 8; o++)
        #pragma unroll
        for (int j = 0; j < 4; j++) acc[o][j] = 0.f;
    for (int chh = 0; chh < 20; chh++) {
        int pb = split*1000 + chh*50;
        __syncthreads();
        for (int i = tid; i < 64*50; i += 256) {
            int k = i / 50, pp = i - k*50;
            sA[k*51 + pp] = d_a[((long)n*KK + k)*PP + pb + pp];
        }
        for (int i = tid; i < 128*50; i += 256) {
            int cc = i / 50, pp = i - cc*50;
            sX2[cc*51 + pp] = x[((long)n*CI + cc)*PP + pb + pp];
        }
        __syncthreads();
        for (int pp = 0; pp < 50; pp++) {
            float av[8];
            #pragma unroll
            for (int o = 0; o < 8; o++) av[o] = sA[(kg*8 + o)*51 + pp];
            #pragma unroll
            for (int j = 0; j < 4; j++) {
                float xv = sX2[(cg + 32*j)*51 + pp];
                #pragma unroll
                for (int o = 0; o < 8; o++) acc[o][j] += av[o]*xv;
            }
        }
    }
    #pragma unroll
    for (int o = 0; o < 8; o++)
        #pragma unroll
        for (int j = 0; j < 4; j++)
            d_vladp[(((long)split*NB + n)*KK + kg*8 + o)*CI + cg + 32*j] = acc[o][j];
}

__global__ void vladreduce_kernel(const float* __restrict__ centers)
{
    __shared__ float sr[128];
    int row = blockIdx.x, n = row >> 6, k = row & 63, cc = threadIdx.x;
    float v = -d_asum[row]*centers[k*CI + cc];
    #pragma unroll
    for (int s = 0; s < 8; s++)
        v += d_vladp[(((long)s*NB + n)*KK + k)*CI + cc];
    sr[cc] = v*v; __syncthreads();
    for (int st = 64; st > 0; st >>= 1) {
        if (cc < st) sr[cc] += sr[cc + st];
        __syncthreads();
    }
    d_feat[(long)n*9216 + k*CI + cc] = v / fmaxf(sqrtf(sr[0]), 1e-12f);
}

__global__ void __launch_bounds__(256) vladglobal_kernel()
{
    __shared__ float sr[256];
    int n = blockIdx.x, tid = threadIdx.x;
    float* f = d_feat + (long)n*9216;
    float s = 0.f;
    for (int i = tid; i < 8192; i += 256) { float v = f[i]; s += v*v; }
    sr[tid] = s; __syncthreads();
    for (int st = 128; st > 0; st >>= 1) {
        if (tid < st) sr[tid] += sr[tid + st];
        __syncthreads();
    }
    float inv = 1.f / fmaxf(sqrtf(sr[0]), 1e-12f);
    for (int i = tid; i < 8192; i += 256) f[i] *= inv;
}

// ------------------------------ tail kernels -------------------------------
__global__ void xfnorm_kernel()
{
    __shared__ float sr[256];
    int n = blockIdx.x, tid = threadIdx.x;
    float v[4]; float s = 0.f;
    #pragma unroll
    for (int i = 0; i < 4; i++) {
        v[i] = d_xf[(long)n*1024 + tid + 256*i];
        s += v[i]*v[i];
    }
    sr[tid] = s; __syncthreads();
    for (int st = 128; st > 0; st >>= 1) {
        if (tid < st) sr[tid] += sr[tid + st];
        __syncthreads();
    }
    float nrm = fmaxf(sqrtf(sr[0]), 1e-12f);
    #pragma unroll
    for (int i = 0; i < 4; i++)
        d_feat[(long)n*9216 + 8192 + tid + 256*i] = v[i] / nrm;
}

__global__ void __launch_bounds__(256) mlp_kernel(
    const float* __restrict__ mw, const float* __restrict__ mb,
    float* __restrict__ out)
{
    __shared__ float sf[9216];
    __shared__ float sr[256];
    int n = blockIdx.x, j = threadIdx.x;
    for (int i = j; i < 9216; i += 256) sf[i] = d_feat[(long)n*9216 + i];
    __syncthreads();
    float acc = mb[j];
    const float4* wr  = (const float4*)(mw + (long)j*9216);
    const float4* sf4 = (const float4*)sf;
    for (int i = 0; i < 2304; i++) {
        float4 w4 = wr[i], f4 = sf4[i];
        acc += w4.x*f4.x + w4.y*f4.y + w4.z*f4.z + w4.w*f4.w;
    }
    sr[j] = acc*acc; __syncthreads();
    for (int st = 128; st > 0; st >>= 1) {
        if (j < st) sr[j] += sr[j + st];
        __syncthreads();
    }
    out[n*256 + j] = acc / fmaxf(sqrtf(sr[0]), 1e-12f);
}

// ---------------------------------------------------------------------------
extern "C" void kernel_launch(void* const* d_in, const int* in_sizes, int n_in,
                              void* d_out, int out_size)
{
    const float* x       = (const float*)d_in[0];
    const float* centers = (const float*)d_in[1];
    const float* cw      = (const float*)d_in[2];
    const float* cb      = (const float*)d_in[3];
    const float* w1      = (const float*)d_in[4];
    const float* b1      = (const float*)d_in[5];
    const float* w2      = (const float*)d_in[6];
    const float* b2      = (const float*)d_in[7];
    const float* w3      = (const float*)d_in[8];
    const float* b3      = (const float*)d_in[9];
    const float* mw      = (const float*)d_in[10];
    const float* mb      = (const float*)d_in[11];
    float* out = (float*)d_out;

    cudaFuncSetAttribute(assign_kernel,
        cudaFuncAttributeMaxDynamicSharedMemorySize, 155904);
    cudaFuncSetAttribute(conv3_mma,
        cudaFuncAttributeMaxDynamicSharedMemorySize, 119104);

    // weight prep — writes device globals internally
    prep_w_h<128><<<3200, 256>>>(w1);
    prep_w_h<256><<<12800, 256>>>(w2);
    prep_w3<<<51200, 256>>>(w3);

    // NetVLAD branch
    assign_kernel<<<dim3(50,16), 256, 155904>>>(x, cw, cb);
    asum_kernel<<<1024, 256>>>();
    vlad_kernel<<<dim3(8,16), 256>>>(x);
    vladreduce_kernel<<<1024, 128>>>(centers);
    vladglobal_kernel<<<16, 256>>>();

    // CNN branch (fp16 2-term convs; conv2 fuses 4x4 pool)
    conv_mma<128,40,200,256,true ><<<dim3(100,4,16), 128, 26880>>>(x, b1);
    conv_mma<256,20,100,512,false><<<dim3(25, 8,16), 128, 26880>>>(nullptr, b2);
    conv3_mma<<<dim3(16,16), 128, 119104>>>(b3);
    xfnorm_kernel<<<16, 256>>>();

    mlp_kernel<<<16, 256>>>(mw, mb, out);
}